// round 1
// baseline (speedup 1.0000x reference)
#include <cuda_runtime.h>
#include <math.h>

#define NT 512
#define D 128
#define H 4
#define DK 32
#define M 5
#define NN 15
#define NV 64

// ---------------- shared-memory layout (floats) ----------------
// persistent: sMask [0,4800), sWW [4800,9920) padded (5,64,16)
// scratch S = sm+9920, extent 45056 floats:
//   NIM  : S+0      (5*128*16 = 10240)   P1-P2
//   Xpad : S+10240  (128*68   = 8704)    P0-P1   (stride-68 padded)
//   P    : S+10240  (10240)              P2
//   K    : S+20480  (8192)               P2-P3
//   Q    : S+28672  (8192)               P2-P3
//   MSG  : S+36864  (8192)               P2-P4
//   A/aw : S+0      (16384)              P3-P4
//   RES  : S+16384  (8192)               P4
//   B    : S+24576  (8192)               P4-P5
//   WMSG/wwBuf : S+32768 (4096)          P4 (reloaded per head)
//   NIM2 : S+0      (10240)              P5
//   Cpad : S+10240  (8704)               P5 (B copy, stride 68)
//   PB   : S+10240  (10240)              P5 (after NIM2)
#define SMEM_FLOATS (9920 + 45056)

static __device__ __forceinline__ float4 f4z() { return make_float4(0.f, 0.f, 0.f, 0.f); }

// NIM[m][dd][N0..N0+3] = sum_nn In[dd][nn] * WW[m][nn][N0..]
static __device__ __forceinline__ void nim_calc(const float* __restrict__ sIn /*stride 68*/,
                                                const float* __restrict__ sWW,
                                                float* __restrict__ sNIM, int tid) {
    for (int t = tid; t < 2560; t += NT) {
        int m = t / 512;
        int r = t - m * 512;
        int dd = r >> 2;
        int N0 = (r & 3) << 2;
        float4 acc = f4z();
        const float* xr = sIn + dd * 68;
        const float* wb = sWW + m * 1024 + N0;
#pragma unroll 4
        for (int nn = 0; nn < 64; nn++) {
            float a = xr[nn];
            float4 bv = *(const float4*)(wb + nn * 16);
            acc.x += a * bv.x; acc.y += a * bv.y; acc.z += a * bv.z; acc.w += a * bv.w;
        }
        *(float4*)(sNIM + m * 2048 + dd * 16 + N0) = acc;
    }
}

// P[m][dd][0..15] = bias[m][dd] + sum_e W[m][dd][e] * NIM[m][e][0..15]
static __device__ __forceinline__ void proj16(const float* __restrict__ Wg,
                                              const float* __restrict__ bg,
                                              const float* __restrict__ sNIM,
                                              float* __restrict__ sP, int tid) {
    for (int t = tid; t < M * D; t += NT) {
        int m = t >> 7, dd = t & 127;
        const float* wrow = Wg + (m * D + dd) * D;
        const float* nbase = sNIM + m * 2048;
        float acc[16];
#pragma unroll
        for (int j = 0; j < 16; j++) acc[j] = 0.f;
#pragma unroll 2
        for (int e = 0; e < D; e++) {
            float w = wrow[e];
            const float4* nv = (const float4*)(nbase + e * 16);
            float4 v0 = nv[0], v1 = nv[1], v2 = nv[2], v3 = nv[3];
            acc[0] += w * v0.x; acc[1] += w * v0.y; acc[2] += w * v0.z; acc[3] += w * v0.w;
            acc[4] += w * v1.x; acc[5] += w * v1.y; acc[6] += w * v1.z; acc[7] += w * v1.w;
            acc[8] += w * v2.x; acc[9] += w * v2.y; acc[10] += w * v2.z; acc[11] += w * v2.w;
            acc[12] += w * v3.x; acc[13] += w * v3.y; acc[14] += w * v3.z; acc[15] += w * v3.w;
        }
        float bias = bg[m * D + dd];
        float* o = sP + m * 2048 + dd * 16;
#pragma unroll
        for (int j = 0; j < 16; j++) o[j] = acc[j] + bias;
    }
}

// permuted mask-mul: dst[d][n] = sum_{m,N} P[m][d][N] * mask[m*15+N][n]
static __device__ __forceinline__ void maskmul_perm(const float* __restrict__ sP,
                                                    const float* __restrict__ sMask,
                                                    float* __restrict__ dst, int tid) {
    for (int t = tid; t < 1024; t += NT) {
        int d = t >> 3, n0 = (t & 7) * 8;
        float4 a0 = f4z(), a1 = f4z();
        int m = 0, N = 0;
        const float* pd = sP + d * 16;
        for (int j = 0; j < 75; j++) {
            float a = pd[m * 2048 + N];
            const float4* mk = (const float4*)(sMask + j * 64 + n0);
            float4 b0 = mk[0], b1 = mk[1];
            a0.x += a * b0.x; a0.y += a * b0.y; a0.z += a * b0.z; a0.w += a * b0.w;
            a1.x += a * b1.x; a1.y += a * b1.y; a1.z += a * b1.z; a1.w += a * b1.w;
            if (++N == 15) { N = 0; m++; }
        }
        *(float4*)(dst + d * 64 + n0) = a0;
        *(float4*)(dst + d * 64 + n0 + 4) = a1;
    }
}

__global__ void __launch_bounds__(NT, 1)
hgt_kernel(const float* __restrict__ node, const float* __restrict__ WWg,
           const float* __restrict__ maskg, const float* __restrict__ Rg,
           const float* __restrict__ AMg,
           const float* __restrict__ WKg, const float* __restrict__ bKg,
           const float* __restrict__ WQg, const float* __restrict__ bQg,
           const float* __restrict__ WMg, const float* __restrict__ bMg,
           const float* __restrict__ WBg, const float* __restrict__ bBg,
           const float* __restrict__ Wup, const float* __restrict__ Wdn,
           const float* __restrict__ Wlf, const float* __restrict__ Wrt,
           float* __restrict__ outp, int nb) {
    const int b = blockIdx.x;
    const int tid = threadIdx.x;
    const int BS = nb * NV;  // stride between d-rows of node_inp
    extern __shared__ float sm[];
    float* sMask = sm;
    float* sWW = sm + 4800;
    float* S = sm + 9920;

    // ---- P0: loads ----
    for (int i = tid; i < 4800; i += NT) sMask[i] = maskg[i];
    for (int i = tid; i < 5120; i += NT) {
        int m = i >> 10, r = i & 1023, nn = r >> 4, N = r & 15;
        sWW[i] = (N < 15) ? WWg[b * 4800 + m * 960 + nn * 15 + N] : 0.f;
    }
    {
        float* sX = S + 10240;
        for (int i = tid; i < 8192; i += NT) {
            int d = i >> 6, nn = i & 63;
            sX[d * 68 + nn] = node[d * BS + b * 64 + nn];
        }
    }
    __syncthreads();

    // ---- P1: NIM = X @ WW ----
    float* sNIM = S;
    nim_calc(S + 10240, sWW, sNIM, tid);
    __syncthreads();

    // ---- P2: projections + mask matmuls ----
    float* sP = S + 10240;
    float* sK = S + 20480;
    float* sQ = S + 28672;
    float* sMSG = S + 36864;

    proj16(WKg, bKg, sNIM, sP, tid);
    __syncthreads();
    maskmul_perm(sP, sMask, sK, tid);
    __syncthreads();

    proj16(WQg, bQg, sNIM, sP, tid);
    __syncthreads();
    maskmul_perm(sP, sMask, sQ, tid);
    __syncthreads();

    proj16(WMg, bMg, sNIM, sP, tid);
    __syncthreads();
    // message uses the FAITHFUL reshape: flat (m,d,N) reinterpreted as (d2, 75)
    for (int t = tid; t < 1024; t += NT) {
        int d2 = t >> 3, n0 = (t & 7) * 8;
        float4 a0 = f4z(), a1 = f4z();
        int f = d2 * 75;
        int m = f / 1920;
        int r = f - m * 1920;
        int dd = r / 15;
        int N = r - dd * 15;
        for (int j = 0; j < 75; j++) {
            float a = sP[m * 2048 + dd * 16 + N];
            const float4* mk = (const float4*)(sMask + j * 64 + n0);
            float4 b0 = mk[0], b1 = mk[1];
            a0.x += a * b0.x; a0.y += a * b0.y; a0.z += a * b0.z; a0.w += a * b0.w;
            a1.x += a * b1.x; a1.y += a * b1.y; a1.z += a * b1.z; a1.w += a * b1.w;
            if (++N == 15) {
                N = 0;
                if (++dd == 128) { dd = 0; ++m; }
            }
        }
        *(float4*)(sMSG + d2 * 64 + n0) = a0;
        *(float4*)(sMSG + d2 * 64 + n0 + 4) = a1;
    }
    __syncthreads();

    // ---- P3: A = Q^T K / sqrt(dk), then softmax(R+A) ----
    float* sA = S;  // NIM + P are dead
    for (int t = tid; t < 2048; t += NT) {
        int h = t >> 9, r = t & 511, i = r >> 3, j0 = (r & 7) * 8;
        float4 a0 = f4z(), a1 = f4z();
        for (int k = 0; k < 32; k++) {
            float a = sQ[(h * 32 + k) * 64 + i];
            const float4* kv = (const float4*)(sK + (h * 32 + k) * 64 + j0);
            float4 b0 = kv[0], b1 = kv[1];
            a0.x += a * b0.x; a0.y += a * b0.y; a0.z += a * b0.z; a0.w += a * b0.w;
            a1.x += a * b1.x; a1.y += a * b1.y; a1.z += a * b1.z; a1.w += a * b1.w;
        }
        const float s = 0.17677669529663687f;  // 1/sqrt(32)
        a0.x *= s; a0.y *= s; a0.z *= s; a0.w *= s;
        a1.x *= s; a1.y *= s; a1.z *= s; a1.w *= s;
        *(float4*)(sA + (h * 64 + i) * 64 + j0) = a0;
        *(float4*)(sA + (h * 64 + i) * 64 + j0 + 4) = a1;
    }
    __syncthreads();

    {
        int warp = tid >> 5, lane = tid & 31;
        for (int r = warp; r < 256; r += NT / 32) {
            float* row = sA + r * 64;
            const float* rrow = Rg + b * 16384 + r * 64;
            float v0 = row[lane] + rrow[lane];
            float v1 = row[lane + 32] + rrow[lane + 32];
            float mx = fmaxf(v0, v1);
#pragma unroll
            for (int o = 16; o > 0; o >>= 1) mx = fmaxf(mx, __shfl_xor_sync(0xffffffffu, mx, o));
            float e0 = expf(v0 - mx), e1 = expf(v1 - mx);
            float sum = e0 + e1;
#pragma unroll
            for (int o = 16; o > 0; o >>= 1) sum += __shfl_xor_sync(0xffffffffu, sum, o);
            float inv = 1.f / sum;
            row[lane] = e0 * inv;
            row[lane + 32] = e1 * inv;
        }
    }
    __syncthreads();

    // aw[0,0] output (tiled * attn_mask) from block 0
    if (b == 0) {
        for (int i = tid; i < 16384; i += NT) {
            int ii = i >> 8, j2 = i & 255;
            outp[D * BS + i] = sA[ii * 64 + (j2 & 63)] * AMg[i];
        }
    }

    // ---- P4: per-head res + attention apply + gelu -> B ----
    float* sRES = S + 16384;
    float* sB = S + 24576;
    float* sWB4 = S + 32768;  // Wmsg (res stage), then ww tile (apply stage)

    for (int h = 0; h < 4; h++) {
        // (re)load Wmsg concat, swizzled [q][ (kk+q)&31 ]
        for (int i = tid; i < 4096; i += NT) {
            int q = i >> 5, kk = i & 31;
            int dir = q >> 5, col = q & 31;
            const float* Wd = (dir == 0) ? Wup : (dir == 1) ? Wdn : (dir == 2) ? Wlf : Wrt;
            sWB4[(q << 5) + ((kk + q) & 31)] = Wd[kk * 32 + col];
        }
        __syncthreads();
        // RES[q][n] = sum_kk Wmsg[kk][q] * MSG[h*32+kk][n]
        for (int t = tid; t < 512; t += NT) {
            int q = t >> 2, n0 = (t & 3) * 16;
            float4 a0 = f4z(), a1 = f4z(), a2 = f4z(), a3 = f4z();
            for (int kk = 0; kk < 32; kk++) {
                float w = sWB4[(q << 5) + ((kk + q) & 31)];
                const float4* mv = (const float4*)(sMSG + (h * 32 + kk) * 64 + n0);
                float4 v0 = mv[0], v1 = mv[1], v2 = mv[2], v3 = mv[3];
                a0.x += w * v0.x; a0.y += w * v0.y; a0.z += w * v0.z; a0.w += w * v0.w;
                a1.x += w * v1.x; a1.y += w * v1.y; a1.z += w * v1.z; a1.w += w * v1.w;
                a2.x += w * v2.x; a2.y += w * v2.y; a2.z += w * v2.z; a2.w += w * v2.w;
                a3.x += w * v3.x; a3.y += w * v3.y; a3.z += w * v3.z; a3.w += w * v3.w;
            }
            float* o = sRES + q * 64 + n0;
            *(float4*)(o) = a0; *(float4*)(o + 4) = a1;
            *(float4*)(o + 8) = a2; *(float4*)(o + 12) = a3;
        }
        __syncthreads();

        for (int i0 = 0; i0 < 64; i0 += 16) {
            // stage1: ww[ii][j2] = aw[h][i0+ii][j2%64] * AM[i0+ii][j2]  (XOR swizzle)
            for (int idx = tid; idx < 4096; idx += NT) {
                int ii = idx >> 8, j2 = idx & 255;
                int i = i0 + ii;
                float ww = sA[(h * 64 + i) * 64 + (j2 & 63)] * AMg[i * 256 + j2];
                sWB4[ii * 256 + (j2 ^ (ii * 4))] = ww;
            }
            __syncthreads();
            // stage2: B[h*32+k][i0+ii] = gelu( sum_j2 ww[ii][j2] * res2[k][j2] )
            for (int t = tid; t < 512; t += NT) {
                int k = t >> 4, ii = t & 15;
                const float* resrow = sRES + k * 256;  // res2 flat == RES flat
                const float* wwrow = sWB4 + ii * 256;
                int sw = ii * 4;
                float acc = 0.f;
#pragma unroll 4
                for (int j2 = 0; j2 < 256; j2 += 4) {
                    float4 rv = *(const float4*)(resrow + j2);
                    float4 wv = *(const float4*)(wwrow + (j2 ^ sw));
                    acc += rv.x * wv.x + rv.y * wv.y + rv.z * wv.z + rv.w * wv.w;
                }
                float g = 0.5f * acc * (1.f + erff(acc * 0.70710678118654752f));
                sB[(h * 32 + k) * 64 + i0 + ii] = g;
            }
            __syncthreads();
        }
    }

    // ---- P5: back-projection + residual ----
    // copy B into padded stride-68 buffer (bank-conflict-free operand)
    {
        float* sC = S + 10240;
        for (int i = tid; i < 8192; i += NT) {
            int d = i >> 6, nn = i & 63;
            sC[d * 68 + nn] = sB[i];
        }
    }
    __syncthreads();
    float* sNIM2 = S;  // aw dead
    nim_calc(S + 10240, sWW, sNIM2, tid);
    __syncthreads();
    float* sPB = S + 10240;  // overwrites the padded copy (done with it)
    proj16(WBg, bBg, sNIM2, sPB, tid);
    __syncthreads();

    for (int t = tid; t < 1024; t += NT) {
        int d = t >> 3, n0 = (t & 7) * 8;
        float4 a0 = f4z(), a1 = f4z();
        int m = 0, N = 0;
        const float* pd = sPB + d * 16;
        for (int j = 0; j < 75; j++) {
            float a = pd[m * 2048 + N];
            const float4* mk = (const float4*)(sMask + j * 64 + n0);
            float4 b0 = mk[0], b1 = mk[1];
            a0.x += a * b0.x; a0.y += a * b0.y; a0.z += a * b0.z; a0.w += a * b0.w;
            a1.x += a * b1.x; a1.y += a * b1.y; a1.z += a * b1.z; a1.w += a * b1.w;
            if (++N == 15) { N = 0; m++; }
        }
        int gi = d * BS + b * 64 + n0;
        float4 r0 = *(const float4*)(node + gi);
        float4 r1 = *(const float4*)(node + gi + 4);
        a0.x += r0.x; a0.y += r0.y; a0.z += r0.z; a0.w += r0.w;
        a1.x += r1.x; a1.y += r1.y; a1.z += r1.z; a1.w += r1.w;
        *(float4*)(outp + gi) = a0;
        *(float4*)(outp + gi + 4) = a1;
    }
}

extern "C" void kernel_launch(void* const* d_in, const int* in_sizes, int n_in,
                              void* d_out, int out_size) {
    const float* node = (const float*)d_in[0];
    const float* WWg = (const float*)d_in[1];
    const float* maskg = (const float*)d_in[2];
    const float* Rg = (const float*)d_in[3];
    const float* AMg = (const float*)d_in[4];
    const float* WKg = (const float*)d_in[5];
    const float* bKg = (const float*)d_in[6];
    const float* WQg = (const float*)d_in[7];
    const float* bQg = (const float*)d_in[8];
    const float* WMg = (const float*)d_in[9];
    const float* bMg = (const float*)d_in[10];
    const float* WBg = (const float*)d_in[11];
    const float* bBg = (const float*)d_in[12];
    const float* Wup = (const float*)d_in[13];
    const float* Wdn = (const float*)d_in[14];
    const float* Wlf = (const float*)d_in[15];
    const float* Wrt = (const float*)d_in[16];
    float* outp = (float*)d_out;

    int nb = in_sizes[0] / (D * NV);  // 1024
    size_t smem = SMEM_FLOATS * sizeof(float);
    cudaFuncSetAttribute(hgt_kernel, cudaFuncAttributeMaxDynamicSharedMemorySize, (int)smem);
    hgt_kernel<<<nb, NT, smem>>>(node, WWg, maskg, Rg, AMg, WKg, bKg, WQg, bQg,
                                 WMg, bMg, WBg, bBg, Wup, Wdn, Wlf, Wrt, outp, nb);
}

// round 3
// speedup vs baseline: 1.8841x; 1.8841x over previous
#include <cuda_runtime.h>
#include <math.h>

#define NT 512
#define D 128
#define H 4
#define DK 32
#define M 5
#define NN 15
#define NV 64

// ---------------- shared-memory layout (floats) ----------------
// sm[0..4800)   : sMask   (persistent)
// sm[4800..9920): sWW     (persistent, padded (5,64,16))
// S = sm + 9920, extent 45056:
//  P0/P1: Xpad S[10240..18560) stride-65 ; NIM S[0..10240)
//  P2   : PK S[10240..20480), PQ S[20480..30720), PM S[30720..40960)
//         K -> S[0..8192), Q -> S[8192..16384), MSG -> S[16384..24576)
//  P3   : A/aw -> S[24576..40960)
//  P4   : RES S[0..8192), B S[8192..16384), Wmsg/ww S[40960..45056), MSG alive
//  P5   : Cpad S[16384..24704) stride-65, NIM2 S[25088..35328), PB S[0..10240)
#define SMEM_FLOATS (9920 + 45056)

static __device__ __forceinline__ float4 f4z() { return make_float4(0.f, 0.f, 0.f, 0.f); }

// NIM[m][dd][n0..+3] = sum_nn In[dd][nn] * WW[m][nn][n0..]; 4-row register tile
static __device__ __forceinline__ void nim_calc4(const float* __restrict__ sIn /*stride65*/,
                                                 const float* __restrict__ sWW,
                                                 float* __restrict__ sNIM, int tid) {
    for (int t = tid; t < 640; t += NT) {
        int m = t >> 7;
        int r = t & 127;
        int dd0 = (r >> 2) << 2;
        int n0 = (r & 3) << 2;
        const float* x0 = sIn + dd0 * 65;
        const float* x1 = x0 + 65;
        const float* x2 = x1 + 65;
        const float* x3 = x2 + 65;
        const float* wb = sWW + m * 1024 + n0;
        float4 a0 = f4z(), a1 = f4z(), a2 = f4z(), a3 = f4z();
#pragma unroll 4
        for (int nn = 0; nn < 64; nn++) {
            float4 w = *(const float4*)(wb + nn * 16);
            float v0 = x0[nn], v1 = x1[nn], v2 = x2[nn], v3 = x3[nn];
            a0.x += v0 * w.x; a0.y += v0 * w.y; a0.z += v0 * w.z; a0.w += v0 * w.w;
            a1.x += v1 * w.x; a1.y += v1 * w.y; a1.z += v1 * w.z; a1.w += v1 * w.w;
            a2.x += v2 * w.x; a2.y += v2 * w.y; a2.z += v2 * w.z; a2.w += v2 * w.w;
            a3.x += v3 * w.x; a3.y += v3 * w.y; a3.z += v3 * w.z; a3.w += v3 * w.w;
        }
        float* o = sNIM + m * 2048 + dd0 * 16 + n0;
        *(float4*)(o) = a0;
        *(float4*)(o + 16) = a1;
        *(float4*)(o + 32) = a2;
        *(float4*)(o + 48) = a3;
    }
}

#define UPD8(acc, W_)                                                           \
    acc[0] += (W_) * n0.x; acc[1] += (W_) * n0.y; acc[2] += (W_) * n0.z;        \
    acc[3] += (W_) * n0.w; acc[4] += (W_) * n1.x; acc[5] += (W_) * n1.y;        \
    acc[6] += (W_) * n1.z; acc[7] += (W_) * n1.w;

// Fused K/Q/M projection: 2-row tile (dd, dd+64), j-split 2. Shares NIM loads 3 ways.
static __device__ __forceinline__ void proj3(const float* __restrict__ WK, const float* __restrict__ bK,
                                             const float* __restrict__ WQ, const float* __restrict__ bQ,
                                             const float* __restrict__ WM, const float* __restrict__ bM,
                                             const float* __restrict__ sNIM,
                                             float* __restrict__ PK, float* __restrict__ PQ,
                                             float* __restrict__ PM, int tid) {
    for (int t = tid; t < 640; t += NT) {
        int pairidx = t >> 1;
        int j0 = (t & 1) << 3;
        int m = pairidx >> 6;
        int dd0 = pairidx & 63;
        const float* nb = sNIM + m * 2048 + j0;
        int ro0 = (m * 128 + dd0) * 128;
        int ro1 = ro0 + 64 * 128;
        float aK0[8], aK1[8], aQ0[8], aQ1[8], aM0[8], aM1[8];
#pragma unroll
        for (int j = 0; j < 8; j++) { aK0[j] = aK1[j] = aQ0[j] = aQ1[j] = aM0[j] = aM1[j] = 0.f; }
        for (int e4 = 0; e4 < 128; e4 += 4) {
            float4 wK0 = *(const float4*)(WK + ro0 + e4);
            float4 wK1 = *(const float4*)(WK + ro1 + e4);
            float4 wQ0 = *(const float4*)(WQ + ro0 + e4);
            float4 wQ1 = *(const float4*)(WQ + ro1 + e4);
            float4 wM0 = *(const float4*)(WM + ro0 + e4);
            float4 wM1 = *(const float4*)(WM + ro1 + e4);
#pragma unroll
            for (int u = 0; u < 4; u++) {
                float4 n0 = *(const float4*)(nb + (e4 + u) * 16);
                float4 n1 = *(const float4*)(nb + (e4 + u) * 16 + 4);
                float fk0 = ((const float*)&wK0)[u];
                float fk1 = ((const float*)&wK1)[u];
                float fq0 = ((const float*)&wQ0)[u];
                float fq1 = ((const float*)&wQ1)[u];
                float fm0 = ((const float*)&wM0)[u];
                float fm1 = ((const float*)&wM1)[u];
                UPD8(aK0, fk0) UPD8(aK1, fk1)
                UPD8(aQ0, fq0) UPD8(aQ1, fq1)
                UPD8(aM0, fm0) UPD8(aM1, fm1)
            }
        }
        float bk0 = bK[m * 128 + dd0], bk1 = bK[m * 128 + dd0 + 64];
        float bq0 = bQ[m * 128 + dd0], bq1 = bQ[m * 128 + dd0 + 64];
        float bm0 = bM[m * 128 + dd0], bm1 = bM[m * 128 + dd0 + 64];
        int o0 = m * 2048 + dd0 * 16 + j0;
        int o1 = o0 + 64 * 16;
#pragma unroll
        for (int j = 0; j < 8; j++) {
            PK[o0 + j] = aK0[j] + bk0; PK[o1 + j] = aK1[j] + bk1;
            PQ[o0 + j] = aQ0[j] + bq0; PQ[o1 + j] = aQ1[j] + bq1;
            PM[o0 + j] = aM0[j] + bm0; PM[o1 + j] = aM1[j] + bm1;
        }
    }
}

// single projection (WB), same tiling
static __device__ __forceinline__ void proj1(const float* __restrict__ W, const float* __restrict__ bg,
                                             const float* __restrict__ sNIM, float* __restrict__ P,
                                             int tid) {
    for (int t = tid; t < 640; t += NT) {
        int pairidx = t >> 1;
        int j0 = (t & 1) << 3;
        int m = pairidx >> 6;
        int dd0 = pairidx & 63;
        const float* nb = sNIM + m * 2048 + j0;
        int ro0 = (m * 128 + dd0) * 128;
        int ro1 = ro0 + 64 * 128;
        float a0[8], a1[8];
#pragma unroll
        for (int j = 0; j < 8; j++) { a0[j] = a1[j] = 0.f; }
        for (int e4 = 0; e4 < 128; e4 += 4) {
            float4 w0 = *(const float4*)(W + ro0 + e4);
            float4 w1 = *(const float4*)(W + ro1 + e4);
#pragma unroll
            for (int u = 0; u < 4; u++) {
                float4 n0 = *(const float4*)(nb + (e4 + u) * 16);
                float4 n1 = *(const float4*)(nb + (e4 + u) * 16 + 4);
                float f0 = ((const float*)&w0)[u];
                float f1 = ((const float*)&w1)[u];
                UPD8(a0, f0) UPD8(a1, f1)
            }
        }
        float b0 = bg[m * 128 + dd0], b1 = bg[m * 128 + dd0 + 64];
        int o0 = m * 2048 + dd0 * 16 + j0;
        int o1 = o0 + 64 * 16;
#pragma unroll
        for (int j = 0; j < 8; j++) {
            P[o0 + j] = a0[j] + b0;
            P[o1 + j] = a1[j] + b1;
        }
    }
}

// permuted mask-mul, 2-row tile (d, d+64)
static __device__ __forceinline__ void maskmul2(const float* __restrict__ sP,
                                                const float* __restrict__ sMask,
                                                float* __restrict__ dst, int tid) {
    for (int t = tid; t < 512; t += NT) {
        int d0 = t >> 3, n0 = (t & 7) << 3;
        float4 a00 = f4z(), a01 = f4z(), a10 = f4z(), a11 = f4z();
        const float* p0 = sP + d0 * 16;
        const float* p1 = sP + (d0 + 64) * 16;
        int m = 0, N = 0;
        for (int j = 0; j < 75; j++) {
            float s0 = p0[m * 2048 + N];
            float s1 = p1[m * 2048 + N];
            float4 b0 = *(const float4*)(sMask + j * 64 + n0);
            float4 b1 = *(const float4*)(sMask + j * 64 + n0 + 4);
            a00.x += s0 * b0.x; a00.y += s0 * b0.y; a00.z += s0 * b0.z; a00.w += s0 * b0.w;
            a01.x += s0 * b1.x; a01.y += s0 * b1.y; a01.z += s0 * b1.z; a01.w += s0 * b1.w;
            a10.x += s1 * b0.x; a10.y += s1 * b0.y; a10.z += s1 * b0.z; a10.w += s1 * b0.w;
            a11.x += s1 * b1.x; a11.y += s1 * b1.y; a11.z += s1 * b1.z; a11.w += s1 * b1.w;
            if (++N == 15) { N = 0; m++; }
        }
        *(float4*)(dst + d0 * 64 + n0) = a00;
        *(float4*)(dst + d0 * 64 + n0 + 4) = a01;
        *(float4*)(dst + (d0 + 64) * 64 + n0) = a10;
        *(float4*)(dst + (d0 + 64) * 64 + n0 + 4) = a11;
    }
}

__global__ void __launch_bounds__(NT, 1)
hgt_kernel(const float* __restrict__ node, const float* __restrict__ WWg,
           const float* __restrict__ maskg, const float* __restrict__ Rg,
           const float* __restrict__ AMg,
           const float* __restrict__ WKg, const float* __restrict__ bKg,
           const float* __restrict__ WQg, const float* __restrict__ bQg,
           const float* __restrict__ WMg, const float* __restrict__ bMg,
           const float* __restrict__ WBg, const float* __restrict__ bBg,
           const float* __restrict__ Wup, const float* __restrict__ Wdn,
           const float* __restrict__ Wlf, const float* __restrict__ Wrt,
           float* __restrict__ outp, int nb) {
    const int b = blockIdx.x;
    const int tid = threadIdx.x;
    const int BS = nb * NV;
    extern __shared__ float sm[];
    float* sMask = sm;
    float* sWW = sm + 4800;
    float* S = sm + 9920;

    // ---- P0: loads ----
    for (int i = tid; i < 4800; i += NT) sMask[i] = maskg[i];
    for (int i = tid; i < 5120; i += NT) {
        int m = i >> 10, r = i & 1023, nn = r >> 4, N = r & 15;
        sWW[i] = (N < 15) ? WWg[b * 4800 + m * 960 + nn * 15 + N] : 0.f;
    }
    {
        float* sX = S + 10240;
        for (int i = tid; i < 8192; i += NT) {
            int d = i >> 6, nn = i & 63;
            sX[d * 65 + nn] = node[d * BS + b * 64 + nn];
        }
    }
    __syncthreads();

    // ---- P1: NIM ----
    float* sNIM = S;
    nim_calc4(S + 10240, sWW, sNIM, tid);
    __syncthreads();

    // ---- P2: fused K/Q/M projection + mask matmuls ----
    float* sPK = S + 10240;
    float* sPQ = S + 20480;
    float* sPM = S + 30720;
    float* sK = S;            // over dead NIM
    float* sQ = S + 8192;     // over dead PK (after K-maskmul)
    float* sMSG = S + 16384;  // over dead PQ tail

    proj3(WKg, bKg, WQg, bQg, WMg, bMg, sNIM, sPK, sPQ, sPM, tid);
    __syncthreads();
    maskmul2(sPK, sMask, sK, tid);
    __syncthreads();
    maskmul2(sPQ, sMask, sQ, tid);
    __syncthreads();
    // message: faithful flat reshape (m,d,N)->(d2,75); 2-row tile with dual cursors
    for (int t = tid; t < 512; t += NT) {
        int d0 = t >> 3, n0 = (t & 7) << 3;
        float4 a00 = f4z(), a01 = f4z(), a10 = f4z(), a11 = f4z();
        int f0 = d0 * 75;
        int m0 = f0 / 1920, r0 = f0 - m0 * 1920, dd0 = r0 / 15, N0 = r0 - dd0 * 15;
        int f1 = (d0 + 64) * 75;
        int m1 = f1 / 1920, r1 = f1 - m1 * 1920, dd1 = r1 / 15, N1 = r1 - dd1 * 15;
        for (int j = 0; j < 75; j++) {
            float s0 = sPM[m0 * 2048 + dd0 * 16 + N0];
            float s1 = sPM[m1 * 2048 + dd1 * 16 + N1];
            float4 b0 = *(const float4*)(sMask + j * 64 + n0);
            float4 b1 = *(const float4*)(sMask + j * 64 + n0 + 4);
            a00.x += s0 * b0.x; a00.y += s0 * b0.y; a00.z += s0 * b0.z; a00.w += s0 * b0.w;
            a01.x += s0 * b1.x; a01.y += s0 * b1.y; a01.z += s0 * b1.z; a01.w += s0 * b1.w;
            a10.x += s1 * b0.x; a10.y += s1 * b0.y; a10.z += s1 * b0.z; a10.w += s1 * b0.w;
            a11.x += s1 * b1.x; a11.y += s1 * b1.y; a11.z += s1 * b1.z; a11.w += s1 * b1.w;
            if (++N0 == 15) { N0 = 0; if (++dd0 == 128) { dd0 = 0; ++m0; } }
            if (++N1 == 15) { N1 = 0; if (++dd1 == 128) { dd1 = 0; ++m1; } }
        }
        *(float4*)(sMSG + d0 * 64 + n0) = a00;
        *(float4*)(sMSG + d0 * 64 + n0 + 4) = a01;
        *(float4*)(sMSG + (d0 + 64) * 64 + n0) = a10;
        *(float4*)(sMSG + (d0 + 64) * 64 + n0 + 4) = a11;
    }
    __syncthreads();

    // ---- P3: A = Q^T K / sqrt(dk) (2-row tile), softmax(R+A) ----
    float* sA = S + 24576;
    for (int t = tid; t < 1024; t += NT) {
        int h = t >> 8, rem = t & 255, i0r = rem >> 3, j0 = (rem & 7) << 3;
        int i1 = i0r + 32;
        float4 a00 = f4z(), a01 = f4z(), a10 = f4z(), a11 = f4z();
        for (int k = 0; k < 32; k++) {
            const float* kr = sK + (h * 32 + k) * 64;
            const float* qr = sQ + (h * 32 + k) * 64;
            float q0 = qr[i0r], q1 = qr[i1];
            float4 b0 = *(const float4*)(kr + j0);
            float4 b1 = *(const float4*)(kr + j0 + 4);
            a00.x += q0 * b0.x; a00.y += q0 * b0.y; a00.z += q0 * b0.z; a00.w += q0 * b0.w;
            a01.x += q0 * b1.x; a01.y += q0 * b1.y; a01.z += q0 * b1.z; a01.w += q0 * b1.w;
            a10.x += q1 * b0.x; a10.y += q1 * b0.y; a10.z += q1 * b0.z; a10.w += q1 * b0.w;
            a11.x += q1 * b1.x; a11.y += q1 * b1.y; a11.z += q1 * b1.z; a11.w += q1 * b1.w;
        }
        const float s = 0.17677669529663687f;
        a00.x *= s; a00.y *= s; a00.z *= s; a00.w *= s;
        a01.x *= s; a01.y *= s; a01.z *= s; a01.w *= s;
        a10.x *= s; a10.y *= s; a10.z *= s; a10.w *= s;
        a11.x *= s; a11.y *= s; a11.z *= s; a11.w *= s;
        *(float4*)(sA + (h * 64 + i0r) * 64 + j0) = a00;
        *(float4*)(sA + (h * 64 + i0r) * 64 + j0 + 4) = a01;
        *(float4*)(sA + (h * 64 + i1) * 64 + j0) = a10;
        *(float4*)(sA + (h * 64 + i1) * 64 + j0 + 4) = a11;
    }
    __syncthreads();

    {
        int warp = tid >> 5, lane = tid & 31;
        for (int r = warp; r < 256; r += NT / 32) {
            float* row = sA + r * 64;
            const float* rrow = Rg + b * 16384 + r * 64;
            float v0 = row[lane] + rrow[lane];
            float v1 = row[lane + 32] + rrow[lane + 32];
            float mx = fmaxf(v0, v1);
#pragma unroll
            for (int o = 16; o > 0; o >>= 1) mx = fmaxf(mx, __shfl_xor_sync(0xffffffffu, mx, o));
            float e0 = expf(v0 - mx), e1 = expf(v1 - mx);
            float sum = e0 + e1;
#pragma unroll
            for (int o = 16; o > 0; o >>= 1) sum += __shfl_xor_sync(0xffffffffu, sum, o);
            float inv = 1.f / sum;
            row[lane] = e0 * inv;
            row[lane + 32] = e1 * inv;
        }
    }
    __syncthreads();

    if (b == 0) {
        for (int i = tid; i < 16384; i += NT) {
            int ii = i >> 8, j2 = i & 255;
            outp[D * BS + i] = sA[ii * 64 + (j2 & 63)] * AMg[i];
        }
    }

    // ---- P4: per-head res + masked attention apply + gelu ----
    float* sRES = S;
    float* sB = S + 8192;
    float* sWB4 = S + 40960;  // Wmsg (res stage) / ww tile (apply stage), shared

    for (int h = 0; h < 4; h++) {
        for (int i = tid; i < 4096; i += NT) {
            int q = i >> 5, kk = i & 31;
            int dir = q >> 5, col = q & 31;
            const float* Wd = (dir == 0) ? Wup : (dir == 1) ? Wdn : (dir == 2) ? Wlf : Wrt;
            sWB4[(q << 5) + ((kk + q) & 31)] = Wd[kk * 32 + col];
        }
        __syncthreads();
        // RES: 2-q tile (q, q+64)
        for (int t = tid; t < 256; t += NT) {
            int q0 = t >> 2, n0 = (t & 3) << 4;
            int q1 = q0 + 64;
            float4 c00 = f4z(), c01 = f4z(), c02 = f4z(), c03 = f4z();
            float4 c10 = f4z(), c11 = f4z(), c12 = f4z(), c13 = f4z();
            for (int kk = 0; kk < 32; kk++) {
                float w0 = sWB4[(q0 << 5) + ((kk + q0) & 31)];
                float w1 = sWB4[(q1 << 5) + ((kk + q1) & 31)];
                const float* mr = sMSG + (h * 32 + kk) * 64 + n0;
                float4 v0 = *(const float4*)(mr);
                float4 v1 = *(const float4*)(mr + 4);
                float4 v2 = *(const float4*)(mr + 8);
                float4 v3 = *(const float4*)(mr + 12);
                c00.x += w0 * v0.x; c00.y += w0 * v0.y; c00.z += w0 * v0.z; c00.w += w0 * v0.w;
                c01.x += w0 * v1.x; c01.y += w0 * v1.y; c01.z += w0 * v1.z; c01.w += w0 * v1.w;
                c02.x += w0 * v2.x; c02.y += w0 * v2.y; c02.z += w0 * v2.z; c02.w += w0 * v2.w;
                c03.x += w0 * v3.x; c03.y += w0 * v3.y; c03.z += w0 * v3.z; c03.w += w0 * v3.w;
                c10.x += w1 * v0.x; c10.y += w1 * v0.y; c10.z += w1 * v0.z; c10.w += w1 * v0.w;
                c11.x += w1 * v1.x; c11.y += w1 * v1.y; c11.z += w1 * v1.z; c11.w += w1 * v1.w;
                c12.x += w1 * v2.x; c12.y += w1 * v2.y; c12.z += w1 * v2.z; c12.w += w1 * v2.w;
                c13.x += w1 * v3.x; c13.y += w1 * v3.y; c13.z += w1 * v3.z; c13.w += w1 * v3.w;
            }
            float* o0 = sRES + q0 * 64 + n0;
            float* o1 = sRES + q1 * 64 + n0;
            *(float4*)(o0) = c00; *(float4*)(o0 + 4) = c01;
            *(float4*)(o0 + 8) = c02; *(float4*)(o0 + 12) = c03;
            *(float4*)(o1) = c10; *(float4*)(o1 + 4) = c11;
            *(float4*)(o1 + 8) = c12; *(float4*)(o1 + 12) = c13;
        }
        __syncthreads();

        for (int i0 = 0; i0 < 64; i0 += 16) {
            // stage1: ww[ii][j2] = aw * attn_mask, XOR-swizzled (overwrites Wmsg)
            for (int idx = tid; idx < 4096; idx += NT) {
                int ii = idx >> 8, j2 = idx & 255;
                int i = i0 + ii;
                float ww = sA[(h * 64 + i) * 64 + (j2 & 63)] * AMg[i * 256 + j2];
                sWB4[ii * 256 + (j2 ^ (ii * 4))] = ww;
            }
            __syncthreads();
            // stage2: 2k x 2ii register tile
            if (tid < 128) {
                int kp = tid >> 3, iip = tid & 7;
                int k0 = kp, k1 = kp + 16;
                int ii0 = iip, ii1 = iip + 8;
                const float* r0 = sRES + k0 * 256;
                const float* r1 = sRES + k1 * 256;
                const float* w0r = sWB4 + ii0 * 256;
                const float* w1r = sWB4 + ii1 * 256;
                int sw0 = ii0 * 4, sw1 = ii1 * 4;
                float a00 = 0.f, a01 = 0.f, a10 = 0.f, a11 = 0.f;
#pragma unroll 4
                for (int j2 = 0; j2 < 256; j2 += 4) {
                    float4 rv0 = *(const float4*)(r0 + j2);
                    float4 rv1 = *(const float4*)(r1 + j2);
                    float4 wv0 = *(const float4*)(w0r + (j2 ^ sw0));
                    float4 wv1 = *(const float4*)(w1r + (j2 ^ sw1));
                    a00 += rv0.x * wv0.x + rv0.y * wv0.y + rv0.z * wv0.z + rv0.w * wv0.w;
                    a01 += rv0.x * wv1.x + rv0.y * wv1.y + rv0.z * wv1.z + rv0.w * wv1.w;
                    a10 += rv1.x * wv0.x + rv1.y * wv0.y + rv1.z * wv0.z + rv1.w * wv0.w;
                    a11 += rv1.x * wv1.x + rv1.y * wv1.y + rv1.z * wv1.z + rv1.w * wv1.w;
                }
                const float c = 0.70710678118654752f;
                sB[(h * 32 + k0) * 64 + i0 + ii0] = 0.5f * a00 * (1.f + erff(a00 * c));
                sB[(h * 32 + k0) * 64 + i0 + ii1] = 0.5f * a01 * (1.f + erff(a01 * c));
                sB[(h * 32 + k1) * 64 + i0 + ii0] = 0.5f * a10 * (1.f + erff(a10 * c));
                sB[(h * 32 + k1) * 64 + i0 + ii1] = 0.5f * a11 * (1.f + erff(a11 * c));
            }
            __syncthreads();
        }
    }

    // ---- P5: back-projection + residual ----
    {
        float* sC = S + 16384;  // stride-65 padded copy of B
        for (int i = tid; i < 8192; i += NT) {
            int d = i >> 6, nn = i & 63;
            sC[d * 65 + nn] = sB[i];
        }
    }
    __syncthreads();
    float* sNIM2 = S + 25088;
    nim_calc4(S + 16384, sWW, sNIM2, tid);
    __syncthreads();
    float* sPB = S;  // over dead RES/B
    proj1(WBg, bBg, sNIM2, sPB, tid);
    __syncthreads();

    for (int t = tid; t < 512; t += NT) {
        int d0 = t >> 3, n0 = (t & 7) << 3;
        float4 a00 = f4z(), a01 = f4z(), a10 = f4z(), a11 = f4z();
        const float* p0 = sPB + d0 * 16;
        const float* p1 = sPB + (d0 + 64) * 16;
        int m = 0, N = 0;
        for (int j = 0; j < 75; j++) {
            float s0 = p0[m * 2048 + N];
            float s1 = p1[m * 2048 + N];
            float4 b0 = *(const float4*)(sMask + j * 64 + n0);
            float4 b1 = *(const float4*)(sMask + j * 64 + n0 + 4);
            a00.x += s0 * b0.x; a00.y += s0 * b0.y; a00.z += s0 * b0.z; a00.w += s0 * b0.w;
            a01.x += s0 * b1.x; a01.y += s0 * b1.y; a01.z += s0 * b1.z; a01.w += s0 * b1.w;
            a10.x += s1 * b0.x; a10.y += s1 * b0.y; a10.z += s1 * b0.z; a10.w += s1 * b0.w;
            a11.x += s1 * b1.x; a11.y += s1 * b1.y; a11.z += s1 * b1.z; a11.w += s1 * b1.w;
            if (++N == 15) { N = 0; m++; }
        }
        int gi0 = d0 * BS + b * 64 + n0;
        int gi1 = (d0 + 64) * BS + b * 64 + n0;
        float4 r00 = *(const float4*)(node + gi0);
        float4 r01 = *(const float4*)(node + gi0 + 4);
        float4 r10 = *(const float4*)(node + gi1);
        float4 r11 = *(const float4*)(node + gi1 + 4);
        a00.x += r00.x; a00.y += r00.y; a00.z += r00.z; a00.w += r00.w;
        a01.x += r01.x; a01.y += r01.y; a01.z += r01.z; a01.w += r01.w;
        a10.x += r10.x; a10.y += r10.y; a10.z += r10.z; a10.w += r10.w;
        a11.x += r11.x; a11.y += r11.y; a11.z += r11.z; a11.w += r11.w;
        *(float4*)(outp + gi0) = a00;
        *(float4*)(outp + gi0 + 4) = a01;
        *(float4*)(outp + gi1) = a10;
        *(float4*)(outp + gi1 + 4) = a11;
    }
}

extern "C" void kernel_launch(void* const* d_in, const int* in_sizes, int n_in,
                              void* d_out, int out_size) {
    const float* node = (const float*)d_in[0];
    const float* WWg = (const float*)d_in[1];
    const float* maskg = (const float*)d_in[2];
    const float* Rg = (const float*)d_in[3];
    const float* AMg = (const float*)d_in[4];
    const float* WKg = (const float*)d_in[5];
    const float* bKg = (const float*)d_in[6];
    const float* WQg = (const float*)d_in[7];
    const float* bQg = (const float*)d_in[8];
    const float* WMg = (const float*)d_in[9];
    const float* bMg = (const float*)d_in[10];
    const float* WBg = (const float*)d_in[11];
    const float* bBg = (const float*)d_in[12];
    const float* Wup = (const float*)d_in[13];
    const float* Wdn = (const float*)d_in[14];
    const float* Wlf = (const float*)d_in[15];
    const float* Wrt = (const float*)d_in[16];
    float* outp = (float*)d_out;

    int nb = in_sizes[0] / (D * NV);
    size_t smem = SMEM_FLOATS * sizeof(float);
    cudaFuncSetAttribute(hgt_kernel, cudaFuncAttributeMaxDynamicSharedMemorySize, (int)smem);
    hgt_kernel<<<nb, NT, smem>>>(node, WWg, maskg, Rg, AMg, WKg, bKg, WQg, bQg,
                                 WMg, bMg, WBg, bBg, Wup, Wdn, Wlf, Wrt, outp, nb);
}

// round 4
// speedup vs baseline: 2.1700x; 1.1517x over previous
#include <cuda_runtime.h>
#include <math.h>

#define NT 512
#define D 128
#define H 4
#define DK 32
#define M 5
#define NN 15
#define NV 64
#define PSTR 17          // padded stride for P buffers
#define PMSZ (128 * PSTR)  // 2176 floats per type

// ---------------- shared memory layout (floats) ----------------
// sm[0..4800)   : sMask (persistent)
// sm[4800..9920): sWW   (persistent, padded (5,64,16))
// S = sm + 9920, extent 47744:
//  P0/P1: Xpad S[10240..18560) stride-65 ; NIM S[0..10240)
//  P2   : PK S[10240..21120), PQ S[21120..32000), PM S[32000..42880)  (stride-17)
//         K -> S[0..8192), Q -> S[10240..18432), MSG -> S[21120..29312)
//  P3   : A/aw -> S[29312..45696)
//  P4   : RES S[0..8192) (swizzled), B S[8192..16384), Wmsg/ww S[16384..20480),
//         partial S[45696..47744), MSG + sA alive
//  P5   : Cpad S[16384..24704) stride-65, NIM2 S[24704..34944), PB S[0..10880)
#define SMEM_FLOATS (9920 + 47744)

static __device__ __forceinline__ float4 f4z() { return make_float4(0.f, 0.f, 0.f, 0.f); }

static __device__ __forceinline__ float gelu_exact(float x) {
    return 0.5f * x * (1.f + erff(x * 0.70710678118654752f));
}

// NIM[m][dd][n0..+3] = sum_nn In[dd][nn] * WW[m][nn][n0..]; 8-row register tile
static __device__ __forceinline__ void nim_calc8(const float* __restrict__ sIn /*stride65*/,
                                                 const float* __restrict__ sWW,
                                                 float* __restrict__ sNIM, int tid) {
    for (int t = tid; t < 320; t += NT) {
        int m = t >> 6;          // 64 items per m
        int r = t & 63;
        int dd0 = (r >> 2) << 3; // 16 groups of 8 rows
        int n0 = (r & 3) << 2;
        const float* xb = sIn + dd0 * 65;
        const float* wb = sWW + m * 1024 + n0;
        float4 a[8];
#pragma unroll
        for (int i = 0; i < 8; i++) a[i] = f4z();
#pragma unroll 4
        for (int nn = 0; nn < 64; nn++) {
            float4 w = *(const float4*)(wb + nn * 16);
#pragma unroll
            for (int i = 0; i < 8; i++) {
                float v = xb[i * 65 + nn];
                a[i].x += v * w.x; a[i].y += v * w.y; a[i].z += v * w.z; a[i].w += v * w.w;
            }
        }
        float* o = sNIM + m * 2048 + dd0 * 16 + n0;
#pragma unroll
        for (int i = 0; i < 8; i++) *(float4*)(o + i * 16) = a[i];
    }
}

#define UPD8(acc, W_)                                                           \
    acc[0] += (W_) * n0.x; acc[1] += (W_) * n0.y; acc[2] += (W_) * n0.z;        \
    acc[3] += (W_) * n0.w; acc[4] += (W_) * n1.x; acc[5] += (W_) * n1.y;        \
    acc[6] += (W_) * n1.z; acc[7] += (W_) * n1.w;

// Fused K/Q/M projection: 2-row tile (dd, dd+64), j-split 2. Shares NIM loads 3 ways.
static __device__ __forceinline__ void proj3(const float* __restrict__ WK, const float* __restrict__ bK,
                                             const float* __restrict__ WQ, const float* __restrict__ bQ,
                                             const float* __restrict__ WM, const float* __restrict__ bM,
                                             const float* __restrict__ sNIM,
                                             float* __restrict__ PK, float* __restrict__ PQ,
                                             float* __restrict__ PM, int tid) {
    for (int t = tid; t < 640; t += NT) {
        int pairidx = t >> 1;
        int j0 = (t & 1) << 3;
        int m = pairidx >> 6;
        int dd0 = pairidx & 63;
        const float* nb = sNIM + m * 2048 + j0;
        int ro0 = (m * 128 + dd0) * 128;
        int ro1 = ro0 + 64 * 128;
        float aK0[8], aK1[8], aQ0[8], aQ1[8], aM0[8], aM1[8];
#pragma unroll
        for (int j = 0; j < 8; j++) { aK0[j] = aK1[j] = aQ0[j] = aQ1[j] = aM0[j] = aM1[j] = 0.f; }
        for (int e4 = 0; e4 < 128; e4 += 4) {
            float4 wK0 = *(const float4*)(WK + ro0 + e4);
            float4 wK1 = *(const float4*)(WK + ro1 + e4);
            float4 wQ0 = *(const float4*)(WQ + ro0 + e4);
            float4 wQ1 = *(const float4*)(WQ + ro1 + e4);
            float4 wM0 = *(const float4*)(WM + ro0 + e4);
            float4 wM1 = *(const float4*)(WM + ro1 + e4);
#pragma unroll
            for (int u = 0; u < 4; u++) {
                float4 n0 = *(const float4*)(nb + (e4 + u) * 16);
                float4 n1 = *(const float4*)(nb + (e4 + u) * 16 + 4);
                float fk0 = ((const float*)&wK0)[u];
                float fk1 = ((const float*)&wK1)[u];
                float fq0 = ((const float*)&wQ0)[u];
                float fq1 = ((const float*)&wQ1)[u];
                float fm0 = ((const float*)&wM0)[u];
                float fm1 = ((const float*)&wM1)[u];
                UPD8(aK0, fk0) UPD8(aK1, fk1)
                UPD8(aQ0, fq0) UPD8(aQ1, fq1)
                UPD8(aM0, fm0) UPD8(aM1, fm1)
            }
        }
        float bk0 = bK[m * 128 + dd0], bk1 = bK[m * 128 + dd0 + 64];
        float bq0 = bQ[m * 128 + dd0], bq1 = bQ[m * 128 + dd0 + 64];
        float bm0 = bM[m * 128 + dd0], bm1 = bM[m * 128 + dd0 + 64];
        int o0 = m * PMSZ + dd0 * PSTR + j0;
        int o1 = o0 + 64 * PSTR;
#pragma unroll
        for (int j = 0; j < 8; j++) {
            PK[o0 + j] = aK0[j] + bk0; PK[o1 + j] = aK1[j] + bk1;
            PQ[o0 + j] = aQ0[j] + bq0; PQ[o1 + j] = aQ1[j] + bq1;
            PM[o0 + j] = aM0[j] + bm0; PM[o1 + j] = aM1[j] + bm1;
        }
    }
}

// single projection (WB): 4-row tile (dd, +32, +64, +96), j-split 2
static __device__ __forceinline__ void proj1(const float* __restrict__ W, const float* __restrict__ bg,
                                             const float* __restrict__ sNIM, float* __restrict__ P,
                                             int tid) {
    for (int t = tid; t < 320; t += NT) {
        int gidx = t >> 1;
        int j0 = (t & 1) << 3;
        int m = gidx >> 5;
        int dd0 = gidx & 31;
        const float* nb = sNIM + m * 2048 + j0;
        int ro[4];
#pragma unroll
        for (int i = 0; i < 4; i++) ro[i] = (m * 128 + dd0 + 32 * i) * 128;
        float a0[8], a1[8], a2[8], a3[8];
#pragma unroll
        for (int j = 0; j < 8; j++) { a0[j] = a1[j] = a2[j] = a3[j] = 0.f; }
        for (int e4 = 0; e4 < 128; e4 += 4) {
            float4 w0 = *(const float4*)(W + ro[0] + e4);
            float4 w1 = *(const float4*)(W + ro[1] + e4);
            float4 w2 = *(const float4*)(W + ro[2] + e4);
            float4 w3 = *(const float4*)(W + ro[3] + e4);
#pragma unroll
            for (int u = 0; u < 4; u++) {
                float4 n0 = *(const float4*)(nb + (e4 + u) * 16);
                float4 n1 = *(const float4*)(nb + (e4 + u) * 16 + 4);
                float f0 = ((const float*)&w0)[u];
                float f1 = ((const float*)&w1)[u];
                float f2 = ((const float*)&w2)[u];
                float f3 = ((const float*)&w3)[u];
                UPD8(a0, f0) UPD8(a1, f1) UPD8(a2, f2) UPD8(a3, f3)
            }
        }
#pragma unroll
        for (int i = 0; i < 4; i++) {
            float* acc = (i == 0) ? a0 : (i == 1) ? a1 : (i == 2) ? a2 : a3;
            float bb = bg[m * 128 + dd0 + 32 * i];
            int o = m * PMSZ + (dd0 + 32 * i) * PSTR + j0;
#pragma unroll
            for (int j = 0; j < 8; j++) P[o + j] = acc[j] + bb;
        }
    }
}

// permuted mask-mul, 4-row tile (d, +32, +64, +96), 4-col
static __device__ __forceinline__ void maskmul4(const float* __restrict__ sP,
                                                const float* __restrict__ sMask,
                                                float* __restrict__ dst, int tid) {
    for (int t = tid; t < 512; t += NT) {
        int dg = t >> 4, n0 = (t & 15) << 2;
        float4 a0 = f4z(), a1 = f4z(), a2 = f4z(), a3 = f4z();
        const float* p0 = sP + dg * PSTR;
        const float* p1 = sP + (dg + 32) * PSTR;
        const float* p2 = sP + (dg + 64) * PSTR;
        const float* p3 = sP + (dg + 96) * PSTR;
        int m = 0, N = 0;
        for (int j = 0; j < 75; j++) {
            int po = m * PMSZ + N;
            float s0 = p0[po], s1 = p1[po], s2 = p2[po], s3 = p3[po];
            float4 bm = *(const float4*)(sMask + j * 64 + n0);
            a0.x += s0 * bm.x; a0.y += s0 * bm.y; a0.z += s0 * bm.z; a0.w += s0 * bm.w;
            a1.x += s1 * bm.x; a1.y += s1 * bm.y; a1.z += s1 * bm.z; a1.w += s1 * bm.w;
            a2.x += s2 * bm.x; a2.y += s2 * bm.y; a2.z += s2 * bm.z; a2.w += s2 * bm.w;
            a3.x += s3 * bm.x; a3.y += s3 * bm.y; a3.z += s3 * bm.z; a3.w += s3 * bm.w;
            if (++N == 15) { N = 0; m++; }
        }
        *(float4*)(dst + dg * 64 + n0) = a0;
        *(float4*)(dst + (dg + 32) * 64 + n0) = a1;
        *(float4*)(dst + (dg + 64) * 64 + n0) = a2;
        *(float4*)(dst + (dg + 96) * 64 + n0) = a3;
    }
}

__global__ void __launch_bounds__(NT, 1)
hgt_kernel(const float* __restrict__ node, const float* __restrict__ WWg,
           const float* __restrict__ maskg, const float* __restrict__ Rg,
           const float* __restrict__ AMg,
           const float* __restrict__ WKg, const float* __restrict__ bKg,
           const float* __restrict__ WQg, const float* __restrict__ bQg,
           const float* __restrict__ WMg, const float* __restrict__ bMg,
           const float* __restrict__ WBg, const float* __restrict__ bBg,
           const float* __restrict__ Wup, const float* __restrict__ Wdn,
           const float* __restrict__ Wlf, const float* __restrict__ Wrt,
           float* __restrict__ outp, int nb) {
    const int b = blockIdx.x;
    const int tid = threadIdx.x;
    const int BS = nb * NV;
    extern __shared__ float sm[];
    float* sMask = sm;
    float* sWW = sm + 4800;
    float* S = sm + 9920;

    // ---- P0: loads ----
    for (int i = tid; i < 4800; i += NT) sMask[i] = maskg[i];
    for (int i = tid; i < 5120; i += NT) {
        int m = i >> 10, r = i & 1023, nn = r >> 4, N = r & 15;
        sWW[i] = (N < 15) ? WWg[b * 4800 + m * 960 + nn * 15 + N] : 0.f;
    }
    {
        float* sX = S + 10240;
        for (int i = tid; i < 8192; i += NT) {
            int d = i >> 6, nn = i & 63;
            sX[d * 65 + nn] = node[d * BS + b * 64 + nn];
        }
    }
    __syncthreads();

    // ---- P1: NIM ----
    float* sNIM = S;
    nim_calc8(S + 10240, sWW, sNIM, tid);
    __syncthreads();

    // ---- P2: fused K/Q/M projection + mask matmuls ----
    float* sPK = S + 10240;
    float* sPQ = S + 21120;
    float* sPM = S + 32000;
    float* sK = S;            // over dead NIM
    float* sQ = S + 10240;    // over dead PK
    float* sMSG = S + 21120;  // over dead PQ

    proj3(WKg, bKg, WQg, bQg, WMg, bMg, sNIM, sPK, sPQ, sPM, tid);
    __syncthreads();
    maskmul4(sPK, sMask, sK, tid);
    __syncthreads();
    maskmul4(sPQ, sMask, sQ, tid);
    __syncthreads();
    // message: faithful flat reshape (m,d,N)->(d2,75); 4-row tile with 4 cursors
    for (int t = tid; t < 512; t += NT) {
        int dg = t >> 4, n0 = (t & 15) << 2;
        float4 a0 = f4z(), a1 = f4z(), a2 = f4z(), a3 = f4z();
        int mC[4], ddC[4], NC[4];
#pragma unroll
        for (int i = 0; i < 4; i++) {
            int f = (dg + 32 * i) * 75;
            mC[i] = f / 1920;
            int r = f - mC[i] * 1920;
            ddC[i] = r / 15;
            NC[i] = r - ddC[i] * 15;
        }
        for (int j = 0; j < 75; j++) {
            float s0 = sPM[mC[0] * PMSZ + ddC[0] * PSTR + NC[0]];
            float s1 = sPM[mC[1] * PMSZ + ddC[1] * PSTR + NC[1]];
            float s2 = sPM[mC[2] * PMSZ + ddC[2] * PSTR + NC[2]];
            float s3 = sPM[mC[3] * PMSZ + ddC[3] * PSTR + NC[3]];
            float4 bm = *(const float4*)(sMask + j * 64 + n0);
            a0.x += s0 * bm.x; a0.y += s0 * bm.y; a0.z += s0 * bm.z; a0.w += s0 * bm.w;
            a1.x += s1 * bm.x; a1.y += s1 * bm.y; a1.z += s1 * bm.z; a1.w += s1 * bm.w;
            a2.x += s2 * bm.x; a2.y += s2 * bm.y; a2.z += s2 * bm.z; a2.w += s2 * bm.w;
            a3.x += s3 * bm.x; a3.y += s3 * bm.y; a3.z += s3 * bm.z; a3.w += s3 * bm.w;
#pragma unroll
            for (int i = 0; i < 4; i++) {
                if (++NC[i] == 15) {
                    NC[i] = 0;
                    if (++ddC[i] == 128) { ddC[i] = 0; ++mC[i]; }
                }
            }
        }
        *(float4*)(sMSG + dg * 64 + n0) = a0;
        *(float4*)(sMSG + (dg + 32) * 64 + n0) = a1;
        *(float4*)(sMSG + (dg + 64) * 64 + n0) = a2;
        *(float4*)(sMSG + (dg + 96) * 64 + n0) = a3;
    }
    __syncthreads();

    // ---- P3: A = Q^T K / sqrt(dk) (2-row tile), softmax(R+A) ----
    float* sA = S + 29312;
    for (int t = tid; t < 1024; t += NT) {
        int h = t >> 8, rem = t & 255, i0r = rem >> 3, j0 = (rem & 7) << 3;
        int i1 = i0r + 32;
        float4 a00 = f4z(), a01 = f4z(), a10 = f4z(), a11 = f4z();
        for (int k = 0; k < 32; k++) {
            const float* kr = sK + (h * 32 + k) * 64;
            const float* qr = sQ + (h * 32 + k) * 64;
            float q0 = qr[i0r], q1 = qr[i1];
            float4 b0 = *(const float4*)(kr + j0);
            float4 b1 = *(const float4*)(kr + j0 + 4);
            a00.x += q0 * b0.x; a00.y += q0 * b0.y; a00.z += q0 * b0.z; a00.w += q0 * b0.w;
            a01.x += q0 * b1.x; a01.y += q0 * b1.y; a01.z += q0 * b1.z; a01.w += q0 * b1.w;
            a10.x += q1 * b0.x; a10.y += q1 * b0.y; a10.z += q1 * b0.z; a10.w += q1 * b0.w;
            a11.x += q1 * b1.x; a11.y += q1 * b1.y; a11.z += q1 * b1.z; a11.w += q1 * b1.w;
        }
        const float s = 0.17677669529663687f;
        a00.x *= s; a00.y *= s; a00.z *= s; a00.w *= s;
        a01.x *= s; a01.y *= s; a01.z *= s; a01.w *= s;
        a10.x *= s; a10.y *= s; a10.z *= s; a10.w *= s;
        a11.x *= s; a11.y *= s; a11.z *= s; a11.w *= s;
        *(float4*)(sA + (h * 64 + i0r) * 64 + j0) = a00;
        *(float4*)(sA + (h * 64 + i0r) * 64 + j0 + 4) = a01;
        *(float4*)(sA + (h * 64 + i1) * 64 + j0) = a10;
        *(float4*)(sA + (h * 64 + i1) * 64 + j0 + 4) = a11;
    }
    __syncthreads();

    {
        int warp = tid >> 5, lane = tid & 31;
        for (int r = warp; r < 256; r += NT / 32) {
            float* row = sA + r * 64;
            const float* rrow = Rg + b * 16384 + r * 64;
            float v0 = row[lane] + rrow[lane];
            float v1 = row[lane + 32] + rrow[lane + 32];
            float mx = fmaxf(v0, v1);
#pragma unroll
            for (int o = 16; o > 0; o >>= 1) mx = fmaxf(mx, __shfl_xor_sync(0xffffffffu, mx, o));
            float e0 = expf(v0 - mx), e1 = expf(v1 - mx);
            float sum = e0 + e1;
#pragma unroll
            for (int o = 16; o > 0; o >>= 1) sum += __shfl_xor_sync(0xffffffffu, sum, o);
            float inv = 1.f / sum;
            row[lane] = e0 * inv;
            row[lane + 32] = e1 * inv;
        }
    }
    __syncthreads();

    if (b == 0) {
        for (int i = tid; i < 16384; i += NT) {
            int ii = i >> 8, j2 = i & 255;
            outp[D * BS + i] = sA[ii * 64 + (j2 & 63)] * AMg[i];
        }
    }

    // ---- P4: per-head res + masked attention apply + gelu ----
    float* sRES = S;            // XOR-swizzled res2 layout [32][256]
    float* sB = S + 8192;
    float* sWB4 = S + 16384;    // Wmsg (res stage) / ww tile (apply), 4096
    float* sPart = S + 45696;   // 2048 split-K partials

    for (int h = 0; h < 4; h++) {
        // load Wmsg swizzled [q][(kk+q)&31]
        for (int i = tid; i < 4096; i += NT) {
            int q = i >> 5, kk = i & 31;
            int dir = q >> 5, col = q & 31;
            const float* Wd = (dir == 0) ? Wup : (dir == 1) ? Wdn : (dir == 2) ? Wlf : Wrt;
            sWB4[(q << 5) + ((kk + q) & 31)] = Wd[kk * 32 + col];
        }
        __syncthreads();
        // RES: 4-q tile (q, +32, +64, +96) x 8n; write into swizzled res2 layout
        if (tid < 256) {
            int qg = tid >> 3, n0 = (tid & 7) << 3;
            float4 c[4][2];
#pragma unroll
            for (int i = 0; i < 4; i++) { c[i][0] = f4z(); c[i][1] = f4z(); }
            for (int kk = 0; kk < 32; kk++) {
                const float* mr = sMSG + (h * 32 + kk) * 64 + n0;
                float4 v0 = *(const float4*)(mr);
                float4 v1 = *(const float4*)(mr + 4);
#pragma unroll
                for (int i = 0; i < 4; i++) {
                    int q = qg + 32 * i;
                    float w = sWB4[(q << 5) + ((kk + q) & 31)];
                    c[i][0].x += w * v0.x; c[i][0].y += w * v0.y;
                    c[i][0].z += w * v0.z; c[i][0].w += w * v0.w;
                    c[i][1].x += w * v1.x; c[i][1].y += w * v1.y;
                    c[i][1].z += w * v1.z; c[i][1].w += w * v1.w;
                }
            }
#pragma unroll
            for (int i = 0; i < 4; i++) {
                int q = qg + 32 * i;
                int kq = q >> 2;                 // res2 row
                int off = ((q & 3) << 6) + n0;   // within-256 offset
                int sw = (kq & 7) << 2;
                float* dstp = sRES + (kq << 8);
                *(float4*)(dstp + (off ^ sw)) = c[i][0];
                *(float4*)(dstp + ((off + 4) ^ sw)) = c[i][1];
            }
        }
        __syncthreads();

        for (int i0 = 0; i0 < 64; i0 += 16) {
            // stage1: ww[ii][j2] = aw * attn_mask, XOR-swizzled (overwrites Wmsg)
            for (int idx = tid; idx < 4096; idx += NT) {
                int ii = idx >> 8, j2 = idx & 255;
                int i = i0 + ii;
                float ww = sA[(h * 64 + i) * 64 + (j2 & 63)] * AMg[i * 256 + j2];
                sWB4[ii * 256 + (j2 ^ (ii << 2))] = ww;
            }
            __syncthreads();
            // stage2: 4-way split-K over j2, 2k x 2ii tiles, all 512 threads
            {
                int g = tid >> 7;       // j2 quarter
                int r = tid & 127;
                int kp = r >> 3, iip = r & 7;
                int k0 = kp, k1 = kp + 16;
                int ii0 = iip, ii1 = iip + 8;
                const float* r0 = sRES + (k0 << 8);
                const float* r1 = sRES + (k1 << 8);
                const float* w0r = sWB4 + (ii0 << 8);
                const float* w1r = sWB4 + (ii1 << 8);
                int sk0 = (k0 & 7) << 2, sk1 = (k1 & 7) << 2;
                int sw0 = ii0 << 2, sw1 = ii1 << 2;
                float a00 = 0.f, a01 = 0.f, a10 = 0.f, a11 = 0.f;
                int jbase = g << 6;
#pragma unroll 4
                for (int jj = 0; jj < 64; jj += 4) {
                    int j2 = jbase + jj;
                    float4 rv0 = *(const float4*)(r0 + (j2 ^ sk0));
                    float4 rv1 = *(const float4*)(r1 + (j2 ^ sk1));
                    float4 wv0 = *(const float4*)(w0r + (j2 ^ sw0));
                    float4 wv1 = *(const float4*)(w1r + (j2 ^ sw1));
                    a00 += rv0.x * wv0.x + rv0.y * wv0.y + rv0.z * wv0.z + rv0.w * wv0.w;
                    a01 += rv0.x * wv1.x + rv0.y * wv1.y + rv0.z * wv1.z + rv0.w * wv1.w;
                    a10 += rv1.x * wv0.x + rv1.y * wv0.y + rv1.z * wv0.z + rv1.w * wv0.w;
                    a11 += rv1.x * wv1.x + rv1.y * wv1.y + rv1.z * wv1.z + rv1.w * wv1.w;
                }
                int gb = g << 9;
                sPart[gb + (k0 << 4) + ii0] = a00;
                sPart[gb + (k0 << 4) + ii1] = a01;
                sPart[gb + (k1 << 4) + ii0] = a10;
                sPart[gb + (k1 << 4) + ii1] = a11;
            }
            __syncthreads();
            // stage3: reduce partials + gelu -> B
            {
                float v = sPart[tid] + sPart[512 + tid] + sPart[1024 + tid] + sPart[1536 + tid];
                int k = tid >> 4, ii = tid & 15;
                sB[(h * 32 + k) * 64 + i0 + ii] = gelu_exact(v);
            }
            __syncthreads();
        }
    }

    // ---- P5: back-projection + residual ----
    {
        float* sC = S + 16384;  // stride-65 padded copy of B
        for (int i = tid; i < 8192; i += NT) {
            int d = i >> 6, nn = i & 63;
            sC[d * 65 + nn] = sB[i];
        }
    }
    __syncthreads();
    float* sNIM2 = S + 24704;
    nim_calc8(S + 16384, sWW, sNIM2, tid);
    __syncthreads();
    float* sPB = S;  // over dead RES/B head
    proj1(WBg, bBg, sNIM2, sPB, tid);
    __syncthreads();

    // final maskmul (4-row) + residual + store
    for (int t = tid; t < 512; t += NT) {
        int dg = t >> 4, n0 = (t & 15) << 2;
        float4 a0 = f4z(), a1 = f4z(), a2 = f4z(), a3 = f4z();
        const float* p0 = sPB + dg * PSTR;
        const float* p1 = sPB + (dg + 32) * PSTR;
        const float* p2 = sPB + (dg + 64) * PSTR;
        const float* p3 = sPB + (dg + 96) * PSTR;
        int m = 0, N = 0;
        for (int j = 0; j < 75; j++) {
            int po = m * PMSZ + N;
            float s0 = p0[po], s1 = p1[po], s2 = p2[po], s3 = p3[po];
            float4 bm = *(const float4*)(sMask + j * 64 + n0);
            a0.x += s0 * bm.x; a0.y += s0 * bm.y; a0.z += s0 * bm.z; a0.w += s0 * bm.w;
            a1.x += s1 * bm.x; a1.y += s1 * bm.y; a1.z += s1 * bm.z; a1.w += s1 * bm.w;
            a2.x += s2 * bm.x; a2.y += s2 * bm.y; a2.z += s2 * bm.z; a2.w += s2 * bm.w;
            a3.x += s3 * bm.x; a3.y += s3 * bm.y; a3.z += s3 * bm.z; a3.w += s3 * bm.w;
            if (++N == 15) { N = 0; m++; }
        }
#pragma unroll
        for (int i = 0; i < 4; i++) {
            float4 acc = (i == 0) ? a0 : (i == 1) ? a1 : (i == 2) ? a2 : a3;
            int d = dg + 32 * i;
            int gi = d * BS + b * 64 + n0;
            float4 rr = *(const float4*)(node + gi);
            acc.x += rr.x; acc.y += rr.y; acc.z += rr.z; acc.w += rr.w;
            *(float4*)(outp + gi) = acc;
        }
    }
}

extern "C" void kernel_launch(void* const* d_in, const int* in_sizes, int n_in,
                              void* d_out, int out_size) {
    const float* node = (const float*)d_in[0];
    const float* WWg = (const float*)d_in[1];
    const float* maskg = (const float*)d_in[2];
    const float* Rg = (const float*)d_in[3];
    const float* AMg = (const float*)d_in[4];
    const float* WKg = (const float*)d_in[5];
    const float* bKg = (const float*)d_in[6];
    const float* WQg = (const float*)d_in[7];
    const float* bQg = (const float*)d_in[8];
    const float* WMg = (const float*)d_in[9];
    const float* bMg = (const float*)d_in[10];
    const float* WBg = (const float*)d_in[11];
    const float* bBg = (const float*)d_in[12];
    const float* Wup = (const float*)d_in[13];
    const float* Wdn = (const float*)d_in[14];
    const float* Wlf = (const float*)d_in[15];
    const float* Wrt = (const float*)d_in[16];
    float* outp = (float*)d_out;

    int nb = in_sizes[0] / (D * NV);
    size_t smem = SMEM_FLOATS * sizeof(float);
    cudaFuncSetAttribute(hgt_kernel, cudaFuncAttributeMaxDynamicSharedMemorySize, (int)smem);
    hgt_kernel<<<nb, NT, smem>>>(node, WWg, maskg, Rg, AMg, WKg, bKg, WQg, bQg,
                                 WMg, bMg, WBg, bBg, Wup, Wdn, Wlf, Wrt, outp, nb);
}

// round 5
// speedup vs baseline: 2.2190x; 1.0226x over previous
#include <cuda_runtime.h>
#include <math.h>

#define NT 512
#define D 128
#define H 4
#define DK 32
#define M 5
#define NN 15
#define NV 64
#define PSTR 17            // padded stride for P buffers
#define PMSZ (128 * PSTR)  // 2176 floats per type

// ---------------- shared memory layout (floats) ----------------
// sm[0..4800)     : sMask (persistent)
// sm[4800..9920)  : sWW   (persistent, padded (5,64,16))
// sm[9920..10048) : sPO offset table (75 ints) + pad
// S = sm + 10048, extent 47744 (same internal plan as R4)
#define SMEM_FLOATS (10048 + 47744)

typedef unsigned long long u64;

static __device__ __forceinline__ u64 bc2(float v) {
    u64 r; asm("mov.b64 %0, {%1, %1};" : "=l"(r) : "f"(v)); return r;
}
static __device__ __forceinline__ void fma2(u64& d, u64 a, u64 b) {
    asm("fma.rn.f32x2 %0, %1, %2, %0;" : "+l"(d) : "l"(a), "l"(b));
}
static __device__ __forceinline__ u64 add2(u64 a, u64 b) {
    u64 r; asm("add.rn.f32x2 %0, %1, %2;" : "=l"(r) : "l"(a), "l"(b)); return r;
}
static __device__ __forceinline__ u64 mul2(u64 a, u64 b) {
    u64 r; asm("mul.rn.f32x2 %0, %1, %2;" : "=l"(r) : "l"(a), "l"(b)); return r;
}
static __device__ __forceinline__ void unpk(u64 v, float& lo, float& hi) {
    asm("mov.b64 {%0, %1}, %2;" : "=f"(lo), "=f"(hi) : "l"(v));
}
static __device__ __forceinline__ float hsum2(u64 v) {
    float lo, hi; unpk(v, lo, hi); return lo + hi;
}
static __device__ __forceinline__ float gelu_exact(float x) {
    return 0.5f * x * (1.f + erff(x * 0.70710678118654752f));
}

// NIM[m][dd][n0..+3] = sum_nn In[dd][nn] * WW[m][nn][n0..]; 8-row tile, f32x2
static __device__ __forceinline__ void nim_calc8(const float* __restrict__ sIn /*stride65*/,
                                                 const float* __restrict__ sWW,
                                                 float* __restrict__ sNIM, int tid) {
    for (int t = tid; t < 320; t += NT) {
        int m = t >> 6;
        int r = t & 63;
        int dd0 = (r >> 2) << 3;
        int n0 = (r & 3) << 2;
        const float* xb = sIn + dd0 * 65;
        const float* wb = sWW + m * 1024 + n0;
        u64 a[8][2];
#pragma unroll
        for (int i = 0; i < 8; i++) { a[i][0] = 0ull; a[i][1] = 0ull; }
#pragma unroll 4
        for (int nn = 0; nn < 64; nn++) {
            ulonglong2 w = *(const ulonglong2*)(wb + nn * 16);
#pragma unroll
            for (int i = 0; i < 8; i++) {
                u64 v = bc2(xb[i * 65 + nn]);
                fma2(a[i][0], v, w.x);
                fma2(a[i][1], v, w.y);
            }
        }
        float* o = sNIM + m * 2048 + dd0 * 16 + n0;
#pragma unroll
        for (int i = 0; i < 8; i++)
            *(ulonglong2*)(o + i * 16) = make_ulonglong2(a[i][0], a[i][1]);
    }
}

#define FMA4(acc, wb_)                       \
    fma2(acc[0], wb_, nv0.x); fma2(acc[1], wb_, nv0.y); \
    fma2(acc[2], wb_, nv1.x); fma2(acc[3], wb_, nv1.y);

// epilogue: unpack 4 u64 (8 cols), add bias, scalar stores (PSTR odd => no u64 store)
static __device__ __forceinline__ void store8(float* __restrict__ P, int o, const u64* acc, float bias) {
#pragma unroll
    for (int p = 0; p < 4; p++) {
        float lo, hi; unpk(acc[p], lo, hi);
        P[o + 2 * p] = lo + bias;
        P[o + 2 * p + 1] = hi + bias;
    }
}

// Fused K/Q/M projection: 2-row tile (dd, dd+64), j-split 2, f32x2
static __device__ __forceinline__ void proj3(const float* __restrict__ WK, const float* __restrict__ bK,
                                             const float* __restrict__ WQ, const float* __restrict__ bQ,
                                             const float* __restrict__ WM, const float* __restrict__ bM,
                                             const float* __restrict__ sNIM,
                                             float* __restrict__ PK, float* __restrict__ PQ,
                                             float* __restrict__ PM, int tid) {
    for (int t = tid; t < 640; t += NT) {
        int pairidx = t >> 1;
        int j0 = (t & 1) << 3;
        int m = pairidx >> 6;
        int dd0 = pairidx & 63;
        const float* nb = sNIM + m * 2048 + j0;
        int ro0 = (m * 128 + dd0) * 128;
        int ro1 = ro0 + 64 * 128;
        u64 aK0[4], aK1[4], aQ0[4], aQ1[4], aM0[4], aM1[4];
#pragma unroll
        for (int j = 0; j < 4; j++) {
            aK0[j] = aK1[j] = aQ0[j] = aQ1[j] = aM0[j] = aM1[j] = 0ull;
        }
        for (int e4 = 0; e4 < 128; e4 += 4) {
            float4 wK0 = *(const float4*)(WK + ro0 + e4);
            float4 wK1 = *(const float4*)(WK + ro1 + e4);
            float4 wQ0 = *(const float4*)(WQ + ro0 + e4);
            float4 wQ1 = *(const float4*)(WQ + ro1 + e4);
            float4 wM0 = *(const float4*)(WM + ro0 + e4);
            float4 wM1 = *(const float4*)(WM + ro1 + e4);
#pragma unroll
            for (int u = 0; u < 4; u++) {
                ulonglong2 nv0 = *(const ulonglong2*)(nb + (e4 + u) * 16);
                ulonglong2 nv1 = *(const ulonglong2*)(nb + (e4 + u) * 16 + 4);
                u64 bk0 = bc2(((const float*)&wK0)[u]);
                u64 bk1 = bc2(((const float*)&wK1)[u]);
                u64 bq0 = bc2(((const float*)&wQ0)[u]);
                u64 bq1 = bc2(((const float*)&wQ1)[u]);
                u64 bm0 = bc2(((const float*)&wM0)[u]);
                u64 bm1 = bc2(((const float*)&wM1)[u]);
                FMA4(aK0, bk0) FMA4(aK1, bk1)
                FMA4(aQ0, bq0) FMA4(aQ1, bq1)
                FMA4(aM0, bm0) FMA4(aM1, bm1)
            }
        }
        int o0 = m * PMSZ + dd0 * PSTR + j0;
        int o1 = o0 + 64 * PSTR;
        store8(PK, o0, aK0, bK[m * 128 + dd0]);
        store8(PK, o1, aK1, bK[m * 128 + dd0 + 64]);
        store8(PQ, o0, aQ0, bQ[m * 128 + dd0]);
        store8(PQ, o1, aQ1, bQ[m * 128 + dd0 + 64]);
        store8(PM, o0, aM0, bM[m * 128 + dd0]);
        store8(PM, o1, aM1, bM[m * 128 + dd0 + 64]);
    }
}

// single projection (WB): 4-row tile, j-split 2, f32x2
static __device__ __forceinline__ void proj1(const float* __restrict__ W, const float* __restrict__ bg,
                                             const float* __restrict__ sNIM, float* __restrict__ P,
                                             int tid) {
    for (int t = tid; t < 320; t += NT) {
        int gidx = t >> 1;
        int j0 = (t & 1) << 3;
        int m = gidx >> 5;
        int dd0 = gidx & 31;
        const float* nb = sNIM + m * 2048 + j0;
        int ro[4];
#pragma unroll
        for (int i = 0; i < 4; i++) ro[i] = (m * 128 + dd0 + 32 * i) * 128;
        u64 a0[4], a1[4], a2[4], a3[4];
#pragma unroll
        for (int j = 0; j < 4; j++) { a0[j] = a1[j] = a2[j] = a3[j] = 0ull; }
        for (int e4 = 0; e4 < 128; e4 += 4) {
            float4 w0 = *(const float4*)(W + ro[0] + e4);
            float4 w1 = *(const float4*)(W + ro[1] + e4);
            float4 w2 = *(const float4*)(W + ro[2] + e4);
            float4 w3 = *(const float4*)(W + ro[3] + e4);
#pragma unroll
            for (int u = 0; u < 4; u++) {
                ulonglong2 nv0 = *(const ulonglong2*)(nb + (e4 + u) * 16);
                ulonglong2 nv1 = *(const ulonglong2*)(nb + (e4 + u) * 16 + 4);
                u64 b0 = bc2(((const float*)&w0)[u]);
                u64 b1 = bc2(((const float*)&w1)[u]);
                u64 b2 = bc2(((const float*)&w2)[u]);
                u64 b3 = bc2(((const float*)&w3)[u]);
                FMA4(a0, b0) FMA4(a1, b1) FMA4(a2, b2) FMA4(a3, b3)
            }
        }
#pragma unroll
        for (int i = 0; i < 4; i++) {
            const u64* acc = (i == 0) ? a0 : (i == 1) ? a1 : (i == 2) ? a2 : a3;
            int o = m * PMSZ + (dd0 + 32 * i) * PSTR + j0;
            store8(P, o, acc, bg[m * 128 + dd0 + 32 * i]);
        }
    }
}

// permuted mask-mul, 4-row tile, f32x2, offset table
static __device__ __forceinline__ void maskmul4(const float* __restrict__ sP,
                                                const float* __restrict__ sMask,
                                                const int* __restrict__ sPO,
                                                float* __restrict__ dst, int tid) {
    for (int t = tid; t < 512; t += NT) {
        int dg = t >> 4, n0 = (t & 15) << 2;
        u64 a0[2], a1[2], a2[2], a3[2];
        a0[0] = a0[1] = a1[0] = a1[1] = a2[0] = a2[1] = a3[0] = a3[1] = 0ull;
        const float* p0 = sP + dg * PSTR;
        const float* p1 = sP + (dg + 32) * PSTR;
        const float* p2 = sP + (dg + 64) * PSTR;
        const float* p3 = sP + (dg + 96) * PSTR;
        for (int j = 0; j < 75; j++) {
            int po = sPO[j];
            u64 s0 = bc2(p0[po]);
            u64 s1 = bc2(p1[po]);
            u64 s2 = bc2(p2[po]);
            u64 s3 = bc2(p3[po]);
            ulonglong2 bm = *(const ulonglong2*)(sMask + j * 64 + n0);
            fma2(a0[0], s0, bm.x); fma2(a0[1], s0, bm.y);
            fma2(a1[0], s1, bm.x); fma2(a1[1], s1, bm.y);
            fma2(a2[0], s2, bm.x); fma2(a2[1], s2, bm.y);
            fma2(a3[0], s3, bm.x); fma2(a3[1], s3, bm.y);
        }
        *(ulonglong2*)(dst + dg * 64 + n0) = make_ulonglong2(a0[0], a0[1]);
        *(ulonglong2*)(dst + (dg + 32) * 64 + n0) = make_ulonglong2(a1[0], a1[1]);
        *(ulonglong2*)(dst + (dg + 64) * 64 + n0) = make_ulonglong2(a2[0], a2[1]);
        *(ulonglong2*)(dst + (dg + 96) * 64 + n0) = make_ulonglong2(a3[0], a3[1]);
    }
}

__global__ void __launch_bounds__(NT, 1)
hgt_kernel(const float* __restrict__ node, const float* __restrict__ WWg,
           const float* __restrict__ maskg, const float* __restrict__ Rg,
           const float* __restrict__ AMg,
           const float* __restrict__ WKg, const float* __restrict__ bKg,
           const float* __restrict__ WQg, const float* __restrict__ bQg,
           const float* __restrict__ WMg, const float* __restrict__ bMg,
           const float* __restrict__ WBg, const float* __restrict__ bBg,
           const float* __restrict__ Wup, const float* __restrict__ Wdn,
           const float* __restrict__ Wlf, const float* __restrict__ Wrt,
           float* __restrict__ outp, int nb) {
    const int b = blockIdx.x;
    const int tid = threadIdx.x;
    const int BS = nb * NV;
    extern __shared__ float sm[];
    float* sMask = sm;
    float* sWW = sm + 4800;
    int* sPO = (int*)(sm + 9920);
    float* S = sm + 10048;

    // ---- P0: loads ----
    for (int i = tid; i < 4800; i += NT) sMask[i] = maskg[i];
    // WW: coalesced read, scatter into padded (5,64,16)
    for (int i = tid; i < 4800; i += NT) {
        int m = i / 960;
        int r = i - m * 960;
        int nn = r / 15;
        int N = r - nn * 15;
        sWW[m * 1024 + nn * 16 + N] = WWg[b * 4800 + i];
    }
    for (int i = tid; i < 320; i += NT) sWW[i * 16 + 15] = 0.f;
    if (tid < 75) sPO[tid] = (tid / 15) * PMSZ + (tid % 15);
    {
        float* sX = S + 10240;
        for (int i = tid; i < 8192; i += NT) {
            int d = i >> 6, nn = i & 63;
            sX[d * 65 + nn] = node[d * BS + b * 64 + nn];
        }
    }
    __syncthreads();

    // ---- P1: NIM ----
    float* sNIM = S;
    nim_calc8(S + 10240, sWW, sNIM, tid);
    __syncthreads();

    // ---- P2: fused K/Q/M projection + mask matmuls ----
    float* sPK = S + 10240;
    float* sPQ = S + 21120;
    float* sPM = S + 32000;
    float* sK = S;
    float* sQ = S + 10240;
    float* sMSG = S + 21120;

    proj3(WKg, bKg, WQg, bQg, WMg, bMg, sNIM, sPK, sPQ, sPM, tid);
    __syncthreads();
    maskmul4(sPK, sMask, sPO, sK, tid);
    __syncthreads();
    maskmul4(sPQ, sMask, sPO, sQ, tid);
    __syncthreads();
    // message: faithful flat reshape (m,d,N)->(d2,75); 4 cursors, f32x2
    for (int t = tid; t < 512; t += NT) {
        int dg = t >> 4, n0 = (t & 15) << 2;
        u64 a0[2], a1[2], a2[2], a3[2];
        a0[0] = a0[1] = a1[0] = a1[1] = a2[0] = a2[1] = a3[0] = a3[1] = 0ull;
        int mC[4], ddC[4], NC[4];
#pragma unroll
        for (int i = 0; i < 4; i++) {
            int f = (dg + 32 * i) * 75;
            mC[i] = f / 1920;
            int r = f - mC[i] * 1920;
            ddC[i] = r / 15;
            NC[i] = r - ddC[i] * 15;
        }
        for (int j = 0; j < 75; j++) {
            u64 s0 = bc2(sPM[mC[0] * PMSZ + ddC[0] * PSTR + NC[0]]);
            u64 s1 = bc2(sPM[mC[1] * PMSZ + ddC[1] * PSTR + NC[1]]);
            u64 s2 = bc2(sPM[mC[2] * PMSZ + ddC[2] * PSTR + NC[2]]);
            u64 s3 = bc2(sPM[mC[3] * PMSZ + ddC[3] * PSTR + NC[3]]);
            ulonglong2 bm = *(const ulonglong2*)(sMask + j * 64 + n0);
            fma2(a0[0], s0, bm.x); fma2(a0[1], s0, bm.y);
            fma2(a1[0], s1, bm.x); fma2(a1[1], s1, bm.y);
            fma2(a2[0], s2, bm.x); fma2(a2[1], s2, bm.y);
            fma2(a3[0], s3, bm.x); fma2(a3[1], s3, bm.y);
#pragma unroll
            for (int i = 0; i < 4; i++) {
                if (++NC[i] == 15) {
                    NC[i] = 0;
                    if (++ddC[i] == 128) { ddC[i] = 0; ++mC[i]; }
                }
            }
        }
        *(ulonglong2*)(sMSG + dg * 64 + n0) = make_ulonglong2(a0[0], a0[1]);
        *(ulonglong2*)(sMSG + (dg + 32) * 64 + n0) = make_ulonglong2(a1[0], a1[1]);
        *(ulonglong2*)(sMSG + (dg + 64) * 64 + n0) = make_ulonglong2(a2[0], a2[1]);
        *(ulonglong2*)(sMSG + (dg + 96) * 64 + n0) = make_ulonglong2(a3[0], a3[1]);
    }
    __syncthreads();

    // ---- P3: A = Q^T K / sqrt(dk), softmax(R+A) ----
    float* sA = S + 29312;
    for (int t = tid; t < 1024; t += NT) {
        int h = t >> 8, rem = t & 255, i0r = rem >> 3, j0 = (rem & 7) << 3;
        int i1 = i0r + 32;
        u64 aR0[4], aR1[4];
#pragma unroll
        for (int j = 0; j < 4; j++) { aR0[j] = aR1[j] = 0ull; }
        for (int k = 0; k < 32; k++) {
            const float* kr = sK + (h * 32 + k) * 64 + j0;
            const float* qr = sQ + (h * 32 + k) * 64;
            u64 q0 = bc2(qr[i0r]);
            u64 q1 = bc2(qr[i1]);
            ulonglong2 nv0 = *(const ulonglong2*)(kr);
            ulonglong2 nv1 = *(const ulonglong2*)(kr + 4);
            FMA4(aR0, q0) FMA4(aR1, q1)
        }
        u64 s2 = bc2(0.17677669529663687f);
#pragma unroll
        for (int j = 0; j < 4; j++) { aR0[j] = mul2(aR0[j], s2); aR1[j] = mul2(aR1[j], s2); }
        float* o0 = sA + (h * 64 + i0r) * 64 + j0;
        float* o1 = sA + (h * 64 + i1) * 64 + j0;
        *(ulonglong2*)(o0) = make_ulonglong2(aR0[0], aR0[1]);
        *(ulonglong2*)(o0 + 4) = make_ulonglong2(aR0[2], aR0[3]);
        *(ulonglong2*)(o1) = make_ulonglong2(aR1[0], aR1[1]);
        *(ulonglong2*)(o1 + 4) = make_ulonglong2(aR1[2], aR1[3]);
    }
    __syncthreads();

    {
        int warp = tid >> 5, lane = tid & 31;
        for (int r = warp; r < 256; r += NT / 32) {
            float* row = sA + r * 64;
            const float* rrow = Rg + b * 16384 + r * 64;
            float v0 = row[lane] + rrow[lane];
            float v1 = row[lane + 32] + rrow[lane + 32];
            float mx = fmaxf(v0, v1);
#pragma unroll
            for (int o = 16; o > 0; o >>= 1) mx = fmaxf(mx, __shfl_xor_sync(0xffffffffu, mx, o));
            float e0 = expf(v0 - mx), e1 = expf(v1 - mx);
            float sum = e0 + e1;
#pragma unroll
            for (int o = 16; o > 0; o >>= 1) sum += __shfl_xor_sync(0xffffffffu, sum, o);
            float inv = 1.f / sum;
            row[lane] = e0 * inv;
            row[lane + 32] = e1 * inv;
        }
    }
    __syncthreads();

    // aw[0,0] output, vectorized
    if (b == 0) {
        for (int idx = tid; idx < 4096; idx += NT) {
            int ii = idx >> 6, j4 = (idx & 63) << 2;
            float4 am = *(const float4*)(AMg + ii * 256 + j4);
            float4 av = *(const float4*)(sA + ii * 64 + (j4 & 63));
            float4 o;
            o.x = av.x * am.x; o.y = av.y * am.y; o.z = av.z * am.z; o.w = av.w * am.w;
            *(float4*)(outp + D * BS + ii * 256 + j4) = o;
        }
    }

    // ---- P4: per-head res + masked attention apply + gelu ----
    float* sRES = S;          // XOR-swizzled res2 [32][256]
    float* sB = S + 8192;
    float* sWB4 = S + 16384;  // Wmsg / ww tile
    float* sPart = S + 45696;

    for (int h = 0; h < 4; h++) {
        for (int i = tid; i < 4096; i += NT) {
            int q = i >> 5, kk = i & 31;
            int dir = q >> 5, col = q & 31;
            const float* Wd = (dir == 0) ? Wup : (dir == 1) ? Wdn : (dir == 2) ? Wlf : Wrt;
            sWB4[(q << 5) + ((kk + q) & 31)] = Wd[kk * 32 + col];
        }
        __syncthreads();
        // RES: 2-q tile (q, q+64) x 8n, 512 threads, f32x2
        {
            int qg = tid >> 3;
            int n0 = (tid & 7) << 3;
            int q0 = qg, q1 = qg + 64;
            u64 c0[4], c1[4];
#pragma unroll
            for (int j = 0; j < 4; j++) { c0[j] = c1[j] = 0ull; }
            for (int kk = 0; kk < 32; kk++) {
                u64 w0 = bc2(sWB4[(q0 << 5) + ((kk + q0) & 31)]);
                u64 w1 = bc2(sWB4[(q1 << 5) + ((kk + q1) & 31)]);
                const float* mr = sMSG + (h * 32 + kk) * 64 + n0;
                ulonglong2 nv0 = *(const ulonglong2*)(mr);
                ulonglong2 nv1 = *(const ulonglong2*)(mr + 4);
                FMA4(c0, w0) FMA4(c1, w1)
            }
#pragma unroll
            for (int i = 0; i < 2; i++) {
                int q = (i == 0) ? q0 : q1;
                const u64* c = (i == 0) ? c0 : c1;
                int kq = q >> 2;
                int off = ((q & 3) << 6) + n0;
                int sw = (kq & 7) << 2;
                float* dstp = sRES + (kq << 8);
                *(ulonglong2*)(dstp + (off ^ sw)) = make_ulonglong2(c[0], c[1]);
                *(ulonglong2*)(dstp + ((off + 4) ^ sw)) = make_ulonglong2(c[2], c[3]);
            }
        }
        __syncthreads();

        for (int i0 = 0; i0 < 64; i0 += 16) {
            // stage1: ww = aw * attn_mask, vectorized, XOR-swizzled
            for (int idx = tid; idx < 1024; idx += NT) {
                int ii = idx >> 6;
                int j4 = (idx & 63) << 2;
                int i = i0 + ii;
                float4 am = *(const float4*)(AMg + i * 256 + j4);
                float4 av = *(const float4*)(sA + (h * 64 + i) * 64 + (j4 & 63));
                float4 w;
                w.x = av.x * am.x; w.y = av.y * am.y; w.z = av.z * am.z; w.w = av.w * am.w;
                *(float4*)(sWB4 + ii * 256 + (j4 ^ (ii << 2))) = w;
            }
            __syncthreads();
            // stage2: 4-way split-K, 2k x 2ii tiles, f32x2
            {
                int g = tid >> 7;
                int r = tid & 127;
                int kp = r >> 3, iip = r & 7;
                int k0 = kp, k1 = kp + 16;
                int ii0 = iip, ii1 = iip + 8;
                const float* r0 = sRES + (k0 << 8);
                const float* r1 = sRES + (k1 << 8);
                const float* w0r = sWB4 + (ii0 << 8);
                const float* w1r = sWB4 + (ii1 << 8);
                int sk0 = (k0 & 7) << 2, sk1 = (k1 & 7) << 2;
                int sw0 = ii0 << 2, sw1 = ii1 << 2;
                u64 a00 = 0ull, a01 = 0ull, a10 = 0ull, a11 = 0ull;
                int jbase = g << 6;
#pragma unroll 4
                for (int jj = 0; jj < 64; jj += 4) {
                    int j2 = jbase + jj;
                    ulonglong2 rv0 = *(const ulonglong2*)(r0 + (j2 ^ sk0));
                    ulonglong2 rv1 = *(const ulonglong2*)(r1 + (j2 ^ sk1));
                    ulonglong2 wv0 = *(const ulonglong2*)(w0r + (j2 ^ sw0));
                    ulonglong2 wv1 = *(const ulonglong2*)(w1r + (j2 ^ sw1));
                    fma2(a00, rv0.x, wv0.x); fma2(a00, rv0.y, wv0.y);
                    fma2(a01, rv0.x, wv1.x); fma2(a01, rv0.y, wv1.y);
                    fma2(a10, rv1.x, wv0.x); fma2(a10, rv1.y, wv0.y);
                    fma2(a11, rv1.x, wv1.x); fma2(a11, rv1.y, wv1.y);
                }
                int gb = g << 9;
                sPart[gb + (k0 << 4) + ii0] = hsum2(a00);
                sPart[gb + (k0 << 4) + ii1] = hsum2(a01);
                sPart[gb + (k1 << 4) + ii0] = hsum2(a10);
                sPart[gb + (k1 << 4) + ii1] = hsum2(a11);
            }
            __syncthreads();
            // stage3: reduce + gelu -> B
            {
                float v = sPart[tid] + sPart[512 + tid] + sPart[1024 + tid] + sPart[1536 + tid];
                int k = tid >> 4, ii = tid & 15;
                sB[(h * 32 + k) * 64 + i0 + ii] = gelu_exact(v);
            }
            __syncthreads();
        }
    }

    // ---- P5: back-projection + residual ----
    {
        float* sC = S + 16384;  // stride-65 padded copy of B
        for (int i = tid; i < 8192; i += NT) {
            int d = i >> 6, nn = i & 63;
            sC[d * 65 + nn] = sB[i];
        }
    }
    __syncthreads();
    float* sNIM2 = S + 24704;
    nim_calc8(S + 16384, sWW, sNIM2, tid);
    __syncthreads();
    float* sPB = S;
    proj1(WBg, bBg, sNIM2, sPB, tid);
    __syncthreads();

    // final maskmul + residual + store, f32x2
    for (int t = tid; t < 512; t += NT) {
        int dg = t >> 4, n0 = (t & 15) << 2;
        u64 a0[2], a1[2], a2[2], a3[2];
        a0[0] = a0[1] = a1[0] = a1[1] = a2[0] = a2[1] = a3[0] = a3[1] = 0ull;
        const float* p0 = sPB + dg * PSTR;
        const float* p1 = sPB + (dg + 32) * PSTR;
        const float* p2 = sPB + (dg + 64) * PSTR;
        const float* p3 = sPB + (dg + 96) * PSTR;
        for (int j = 0; j < 75; j++) {
            int po = sPO[j];
            u64 s0 = bc2(p0[po]);
            u64 s1 = bc2(p1[po]);
            u64 s2 = bc2(p2[po]);
            u64 s3 = bc2(p3[po]);
            ulonglong2 bm = *(const ulonglong2*)(sMask + j * 64 + n0);
            fma2(a0[0], s0, bm.x); fma2(a0[1], s0, bm.y);
            fma2(a1[0], s1, bm.x); fma2(a1[1], s1, bm.y);
            fma2(a2[0], s2, bm.x); fma2(a2[1], s2, bm.y);
            fma2(a3[0], s3, bm.x); fma2(a3[1], s3, bm.y);
        }
#pragma unroll
        for (int i = 0; i < 4; i++) {
            const u64* acc = (i == 0) ? a0 : (i == 1) ? a1 : (i == 2) ? a2 : a3;
            int d = dg + 32 * i;
            int gi = d * BS + b * 64 + n0;
            ulonglong2 rr = *(const ulonglong2*)(node + gi);
            *(ulonglong2*)(outp + gi) =
                make_ulonglong2(add2(acc[0], rr.x), add2(acc[1], rr.y));
        }
    }
}

extern "C" void kernel_launch(void* const* d_in, const int* in_sizes, int n_in,
                              void* d_out, int out_size) {
    const float* node = (const float*)d_in[0];
    const float* WWg = (const float*)d_in[1];
    const float* maskg = (const float*)d_in[2];
    const float* Rg = (const float*)d_in[3];
    const float* AMg = (const float*)d_in[4];
    const float* WKg = (const float*)d_in[5];
    const float* bKg = (const float*)d_in[6];
    const float* WQg = (const float*)d_in[7];
    const float* bQg = (const float*)d_in[8];
    const float* WMg = (const float*)d_in[9];
    const float* bMg = (const float*)d_in[10];
    const float* WBg = (const float*)d_in[11];
    const float* bBg = (const float*)d_in[12];
    const float* Wup = (const float*)d_in[13];
    const float* Wdn = (const float*)d_in[14];
    const float* Wlf = (const float*)d_in[15];
    const float* Wrt = (const float*)d_in[16];
    float* outp = (float*)d_out;

    int nb = in_sizes[0] / (D * NV);
    size_t smem = SMEM_FLOATS * sizeof(float);
    cudaFuncSetAttribute(hgt_kernel, cudaFuncAttributeMaxDynamicSharedMemorySize, (int)smem);
    hgt_kernel<<<nb, NT, smem>>>(node, WWg, maskg, Rg, AMg, WKg, bKg, WQg, bQg,
                                 WMg, bMg, WBg, bBg, Wup, Wdn, Wlf, Wrt, outp, nb);
}